// round 2
// baseline (speedup 1.0000x reference)
#include <cuda_runtime.h>
#include <math.h>
#include <stddef.h>

// Problem constants
#define B_    2
#define S_    2048
#define D_    1024
#define H_    16
#define DK_   64
#define DFF_  4096
#define M_    (B_ * S_)          // 4096 rows
#define EPS_  1e-6f

// ---------------------------------------------------------------------------
// Scratch (device globals: allocation-free workaround per harness rules)
// ---------------------------------------------------------------------------
__device__ float g_n  [(size_t)M_ * D_];
__device__ float g_q  [(size_t)M_ * D_];
__device__ float g_k  [(size_t)M_ * D_];
__device__ float g_v  [(size_t)M_ * D_];
__device__ float g_ctx[(size_t)M_ * D_];
__device__ float g_x1 [(size_t)M_ * D_];
__device__ float g_n2 [(size_t)M_ * D_];
__device__ float g_ff1[(size_t)M_ * DFF_];
__device__ float g_scores[(size_t)B_ * H_ * S_ * S_];   // 537 MB

// ---------------------------------------------------------------------------
// Block-wide allreduce helpers (256 threads = 8 warps)
// ---------------------------------------------------------------------------
__device__ __forceinline__ float allreduce_sum(float v, float* sh) {
    #pragma unroll
    for (int o = 16; o > 0; o >>= 1) v += __shfl_xor_sync(0xffffffffu, v, o);
    int lane = threadIdx.x & 31, wid = threadIdx.x >> 5;
    if (lane == 0) sh[wid] = v;
    __syncthreads();
    if (wid == 0) {
        float r = sh[lane & 7];
        #pragma unroll
        for (int o = 4; o > 0; o >>= 1) r += __shfl_xor_sync(0xffffffffu, r, o);
        // note: with sh[lane&7] replication the xor-4/2/1 tree sums each of 8 once
        if (lane == 0) sh[0] = r;
    }
    __syncthreads();
    float r = sh[0];
    __syncthreads();
    return r;
}

__device__ __forceinline__ float allreduce_max(float v, float* sh) {
    #pragma unroll
    for (int o = 16; o > 0; o >>= 1) v = fmaxf(v, __shfl_xor_sync(0xffffffffu, v, o));
    int lane = threadIdx.x & 31, wid = threadIdx.x >> 5;
    if (lane == 0) sh[wid] = v;
    __syncthreads();
    if (wid == 0) {
        float r = sh[lane & 7];
        #pragma unroll
        for (int o = 4; o > 0; o >>= 1) r = fmaxf(r, __shfl_xor_sync(0xffffffffu, r, o));
        if (lane == 0) sh[0] = r;
    }
    __syncthreads();
    float r = sh[0];
    __syncthreads();
    return r;
}

// Wait: allreduce_sum with sh[lane&7] would double-count under xor-4 since both
// lanes hold valid (different) partials and reduce correctly — lanes l and l^4
// hold sh[l&7] and sh[(l&7)^4]; the 4/2/1 xor tree over the low 3 bits combines
// all 8 distinct partials exactly once per lane. Correct for sum and max.

// ---------------------------------------------------------------------------
// LayerNorm: one block (256 thr) per row of D=1024. ddof=1, eps on std.
// ---------------------------------------------------------------------------
__global__ void layernorm_kernel(const float* __restrict__ x,
                                 const float* __restrict__ alpha,
                                 const float* __restrict__ beta,
                                 float* __restrict__ out) {
    __shared__ float sh[32];
    size_t row = blockIdx.x;
    const float* p = x + row * D_;
    float v[4];
    float s = 0.f;
    #pragma unroll
    for (int i = 0; i < 4; i++) { v[i] = p[threadIdx.x + i * 256]; s += v[i]; }
    s = allreduce_sum(s, sh);
    float mean = s * (1.0f / D_);
    float var = 0.f;
    #pragma unroll
    for (int i = 0; i < 4; i++) { float d = v[i] - mean; var += d * d; }
    var = allreduce_sum(var, sh) * (1.0f / (D_ - 1));   // Bessel correction
    float scale = alpha[0] / (sqrtf(var) + EPS_);       // eps added to std
    float bias = beta[0];
    float* o = out + row * D_;
    #pragma unroll
    for (int i = 0; i < 4; i++)
        o[threadIdx.x + i * 256] = (v[i] - mean) * scale + bias;
}

// ---------------------------------------------------------------------------
// SGEMM: C[M,N] = A[M,K] @ W[K,N] + bias, optional epilogue.
// 128x128 block tile, BK=8, 256 threads, 8x8 microtile.
// EPI: 0 = none, 1 = relu, 2 = add residual R
// ---------------------------------------------------------------------------
template <int EPI>
__global__ void sgemm_bias(const float* __restrict__ A, const float* __restrict__ W,
                           const float* __restrict__ bias, const float* __restrict__ R,
                           float* __restrict__ C, int M, int N, int K) {
    const int BM = 128, BN = 128, BK = 8;
    __shared__ float As[BK][BM];
    __shared__ float Bs[BK][BN];

    int bx = blockIdx.x;   // N tile
    int by = blockIdx.y;   // M tile
    int tid = threadIdx.x; // 256
    int tx = tid & 15, ty = tid >> 4;

    float acc[8][8] = {};

    const float* Aptr = A + (size_t)(by * BM) * K;
    const float* Wptr = W + bx * BN;

    int arow = tid >> 1;           // 0..127
    int acol = (tid & 1) * 4;      // 0 or 4
    int brow = tid >> 5;           // 0..7
    int bcol = (tid & 31) * 4;     // 0..124

    for (int k0 = 0; k0 < K; k0 += BK) {
        float4 a4 = *(const float4*)(Aptr + (size_t)arow * K + k0 + acol);
        As[acol + 0][arow] = a4.x;
        As[acol + 1][arow] = a4.y;
        As[acol + 2][arow] = a4.z;
        As[acol + 3][arow] = a4.w;
        float4 b4 = *(const float4*)(Wptr + (size_t)(k0 + brow) * N + bcol);
        *(float4*)&Bs[brow][bcol] = b4;
        __syncthreads();

        #pragma unroll
        for (int kk = 0; kk < BK; kk++) {
            float af[8], bf[8];
            *(float4*)&af[0] = *(const float4*)&As[kk][ty * 8];
            *(float4*)&af[4] = *(const float4*)&As[kk][ty * 8 + 4];
            *(float4*)&bf[0] = *(const float4*)&Bs[kk][tx * 8];
            *(float4*)&bf[4] = *(const float4*)&Bs[kk][tx * 8 + 4];
            #pragma unroll
            for (int i = 0; i < 8; i++)
                #pragma unroll
                for (int j = 0; j < 8; j++)
                    acc[i][j] += af[i] * bf[j];
        }
        __syncthreads();
    }

    int crow0 = by * BM + ty * 8;
    int ccol0 = bx * BN + tx * 8;
    #pragma unroll
    for (int i = 0; i < 8; i++) {
        size_t r = (size_t)(crow0 + i);
        #pragma unroll
        for (int j = 0; j < 8; j += 4) {
            int c = ccol0 + j;
            float4 o;
            o.x = acc[i][j + 0] + bias[c + 0];
            o.y = acc[i][j + 1] + bias[c + 1];
            o.z = acc[i][j + 2] + bias[c + 2];
            o.w = acc[i][j + 3] + bias[c + 3];
            if (EPI == 1) {
                o.x = fmaxf(o.x, 0.f); o.y = fmaxf(o.y, 0.f);
                o.z = fmaxf(o.z, 0.f); o.w = fmaxf(o.w, 0.f);
            } else if (EPI == 2) {
                float4 r4 = *(const float4*)(R + r * (size_t)N + c);
                o.x += r4.x; o.y += r4.y; o.z += r4.z; o.w += r4.w;
            }
            *(float4*)(C + r * (size_t)N + c) = o;
        }
    }
}

// ---------------------------------------------------------------------------
// Attention scores: scores[bh,q,k] = (Q[b,q,h,:]·K[b,k,h,:]) / 8, masked.
// grid (S/64 ktiles, S/64 qtiles, B*H), 256 threads, 64x64 tile, full DK=64.
// ---------------------------------------------------------------------------
__global__ void attn_scores_kernel(const float* __restrict__ q,
                                   const float* __restrict__ k,
                                   const int* __restrict__ mask,
                                   float* __restrict__ scores) {
    __shared__ float Qs[64][68];
    __shared__ float Ks[64][68];
    int kt = blockIdx.x, qt = blockIdx.y, bh = blockIdx.z;
    int b = bh >> 4, h = bh & 15;
    int tid = threadIdx.x;

    #pragma unroll
    for (int it = 0; it < 4; it++) {
        int idx = tid + it * 256;            // 0..1023
        int r = idx >> 4;                    // 0..63
        int c = (idx & 15) << 2;             // 0..60 step 4
        *(float4*)&Qs[r][c] =
            *(const float4*)(q + ((size_t)(b * S_ + qt * 64 + r)) * D_ + h * DK_ + c);
        *(float4*)&Ks[r][c] =
            *(const float4*)(k + ((size_t)(b * S_ + kt * 64 + r)) * D_ + h * DK_ + c);
    }
    __syncthreads();

    int tx = tid & 15, ty = tid >> 4;
    float acc[4][4] = {};
    #pragma unroll 8
    for (int kk = 0; kk < 64; kk++) {
        float qf[4], kf[4];
        #pragma unroll
        for (int i = 0; i < 4; i++) qf[i] = Qs[ty * 4 + i][kk];
        #pragma unroll
        for (int j = 0; j < 4; j++) kf[j] = Ks[tx * 4 + j][kk];
        #pragma unroll
        for (int i = 0; i < 4; i++)
            #pragma unroll
            for (int j = 0; j < 4; j++)
                acc[i][j] += qf[i] * kf[j];
    }

    const float scale = 0.125f;   // 1/sqrt(64)
    #pragma unroll
    for (int i = 0; i < 4; i++) {
        int qrow = qt * 64 + ty * 4 + i;
        float* dst = scores + ((size_t)bh * S_ + qrow) * S_ + kt * 64;
        #pragma unroll
        for (int j = 0; j < 4; j++) {
            int kcol = kt * 64 + tx * 4 + j;
            int mm = mask[b * S_ + kcol];
            dst[tx * 4 + j] = mm ? acc[i][j] * scale : -1e9f;
        }
    }
}

// ---------------------------------------------------------------------------
// Row softmax over S=2048, one block (256 thr) per row (B*H*S rows).
// ---------------------------------------------------------------------------
__global__ void softmax_kernel(float* __restrict__ scores) {
    __shared__ float sh[32];
    size_t row = blockIdx.x;
    float* p = scores + row * (size_t)S_;
    float v[8];
    float m = -INFINITY;
    #pragma unroll
    for (int i = 0; i < 8; i++) {
        v[i] = p[threadIdx.x + i * 256];
        m = fmaxf(m, v[i]);
    }
    m = allreduce_max(m, sh);
    float s = 0.f;
    #pragma unroll
    for (int i = 0; i < 8; i++) { v[i] = __expf(v[i] - m); s += v[i]; }
    s = allreduce_sum(s, sh);
    float inv = 1.0f / s;
    #pragma unroll
    for (int i = 0; i < 8; i++) p[threadIdx.x + i * 256] = v[i] * inv;
}

// ---------------------------------------------------------------------------
// PV: ctx[b,q,h,:] = sum_k attn[bh,q,k] * V[b,k,h,:]
// grid (S/64 qtiles, B*H), 256 threads, 64q x 64d tile, k in tiles of 64.
// ---------------------------------------------------------------------------
__global__ void attn_av_kernel(const float* __restrict__ attn,
                               const float* __restrict__ v,
                               float* __restrict__ ctx) {
    __shared__ float As[64][68];
    __shared__ float Vs[64][68];
    int qt = blockIdx.x, bh = blockIdx.y;
    int b = bh >> 4, h = bh & 15;
    int tid = threadIdx.x;
    int tx = tid & 15, ty = tid >> 4;

    float acc[4][4] = {};
    for (int k0 = 0; k0 < S_; k0 += 64) {
        #pragma unroll
        for (int it = 0; it < 4; it++) {
            int idx = tid + it * 256;
            int r = idx >> 4;
            int c = (idx & 15) << 2;
            *(float4*)&As[r][c] =
                *(const float4*)(attn + ((size_t)bh * S_ + qt * 64 + r) * S_ + k0 + c);
            *(float4*)&Vs[r][c] =
                *(const float4*)(v + ((size_t)(b * S_ + k0 + r)) * D_ + h * DK_ + c);
        }
        __syncthreads();
        #pragma unroll 8
        for (int kk = 0; kk < 64; kk++) {
            float af[4];
            #pragma unroll
            for (int i = 0; i < 4; i++) af[i] = As[ty * 4 + i][kk];
            float4 bv = *(const float4*)&Vs[kk][tx * 4];
            float bf[4] = {bv.x, bv.y, bv.z, bv.w};
            #pragma unroll
            for (int i = 0; i < 4; i++)
                #pragma unroll
                for (int j = 0; j < 4; j++)
                    acc[i][j] += af[i] * bf[j];
        }
        __syncthreads();
    }

    #pragma unroll
    for (int i = 0; i < 4; i++) {
        int qrow = qt * 64 + ty * 4 + i;
        float* dst = ctx + ((size_t)(b * S_ + qrow)) * D_ + h * DK_ + tx * 4;
        float4 o = {acc[i][0], acc[i][1], acc[i][2], acc[i][3]};
        *(float4*)dst = o;
    }
}

// ---------------------------------------------------------------------------
// Launch: 11 kernels total, all on default stream (graph-capturable).
// ---------------------------------------------------------------------------
extern "C" void kernel_launch(void* const* d_in, const int* in_sizes, int n_in,
                              void* d_out, int out_size) {
    const float* x    = (const float*)d_in[0];
    const int*   mask = (const int*)  d_in[1];
    const float* wq   = (const float*)d_in[2];
    const float* bq   = (const float*)d_in[3];
    const float* wk   = (const float*)d_in[4];
    const float* bk   = (const float*)d_in[5];
    const float* wv   = (const float*)d_in[6];
    const float* bv   = (const float*)d_in[7];
    const float* wo   = (const float*)d_in[8];
    const float* bo   = (const float*)d_in[9];
    const float* w1   = (const float*)d_in[10];
    const float* b1   = (const float*)d_in[11];
    const float* w2   = (const float*)d_in[12];
    const float* b2   = (const float*)d_in[13];
    const float* a1   = (const float*)d_in[14];
    const float* g1   = (const float*)d_in[15];
    const float* a2   = (const float*)d_in[16];
    const float* g2   = (const float*)d_in[17];
    float* out = (float*)d_out;

    float *n_, *q_, *k_, *v_, *ctx_, *x1_, *n2_, *ff1_, *sc_;
    cudaGetSymbolAddress((void**)&n_,   g_n);
    cudaGetSymbolAddress((void**)&q_,   g_q);
    cudaGetSymbolAddress((void**)&k_,   g_k);
    cudaGetSymbolAddress((void**)&v_,   g_v);
    cudaGetSymbolAddress((void**)&ctx_, g_ctx);
    cudaGetSymbolAddress((void**)&x1_,  g_x1);
    cudaGetSymbolAddress((void**)&n2_,  g_n2);
    cudaGetSymbolAddress((void**)&ff1_, g_ff1);
    cudaGetSymbolAddress((void**)&sc_,  g_scores);

    // ---- sublayer 1: pre-norm attention ----
    layernorm_kernel<<<M_, 256>>>(x, a1, g1, n_);

    dim3 gproj(D_ / 128, M_ / 128);   // (8, 32)
    sgemm_bias<0><<<gproj, 256>>>(n_, wq, bq, nullptr, q_, M_, D_, D_);
    sgemm_bias<0><<<gproj, 256>>>(n_, wk, bk, nullptr, k_, M_, D_, D_);
    sgemm_bias<0><<<gproj, 256>>>(n_, wv, bv, nullptr, v_, M_, D_, D_);

    attn_scores_kernel<<<dim3(S_ / 64, S_ / 64, B_ * H_), 256>>>(q_, k_, mask, sc_);
    softmax_kernel<<<B_ * H_ * S_, 256>>>(sc_);
    attn_av_kernel<<<dim3(S_ / 64, B_ * H_), 256>>>(sc_, v_, ctx_);

    sgemm_bias<2><<<gproj, 256>>>(ctx_, wo, bo, x, x1_, M_, D_, D_);   // + residual x

    // ---- sublayer 2: pre-norm FFN ----
    layernorm_kernel<<<M_, 256>>>(x1_, a2, g2, n2_);
    sgemm_bias<1><<<dim3(DFF_ / 128, M_ / 128), 256>>>(n2_, w1, b1, nullptr, ff1_,
                                                       M_, DFF_, D_);   // relu
    sgemm_bias<2><<<dim3(D_ / 128, M_ / 128), 256>>>(ff1_, w2, b2, x1_, out,
                                                     M_, D_, DFF_);     // + residual x1
}

// round 3
// speedup vs baseline: 1.8703x; 1.8703x over previous
#include <cuda_runtime.h>
#include <math.h>
#include <stddef.h>
#include <stdint.h>

// Problem constants
#define B_    2
#define S_    2048
#define D_    1024
#define H_    16
#define DK_   64
#define DFF_  4096
#define M_    (B_ * S_)          // 4096 rows
#define EPS_  1e-6f

// ---------------------------------------------------------------------------
// Scratch (device globals: allocation-free workaround per harness rules)
// ---------------------------------------------------------------------------
__device__ float g_n  [(size_t)M_ * D_];
__device__ float g_q  [(size_t)M_ * D_];
__device__ float g_k  [(size_t)M_ * D_];
__device__ float g_v  [(size_t)M_ * D_];
__device__ float g_ctx[(size_t)M_ * D_];
__device__ float g_x1 [(size_t)M_ * D_];
__device__ float g_n2 [(size_t)M_ * D_];
__device__ float g_ff1[(size_t)M_ * DFF_];
__device__ float g_scores[(size_t)B_ * H_ * S_ * S_];   // 537 MB

// ---------------------------------------------------------------------------
// tf32 helpers
// ---------------------------------------------------------------------------
__device__ __forceinline__ float to_tf32(float x) {
    uint32_t u;
    asm("cvt.rna.tf32.f32 %0, %1;" : "=r"(u) : "f"(x));
    return __uint_as_float(u);
}

__device__ __forceinline__ void mma_tf32(float* c, const uint32_t* a, const uint32_t* b) {
    asm volatile(
        "mma.sync.aligned.m16n8k8.row.col.f32.tf32.tf32.f32 "
        "{%0,%1,%2,%3}, {%4,%5,%6,%7}, {%8,%9}, {%0,%1,%2,%3};"
        : "+f"(c[0]), "+f"(c[1]), "+f"(c[2]), "+f"(c[3])
        : "r"(a[0]), "r"(a[1]), "r"(a[2]), "r"(a[3]), "r"(b[0]), "r"(b[1]));
}

// ---------------------------------------------------------------------------
// Batched tf32 tensor-core GEMM.
//   C[bh][M,N] = A[bh][M,K] @ B[bh][K,N] (+ epilogue)
// TRB=0: B stored row-major [K,N] (ldb = row stride)
// TRB=1: B stored as [N,K] row-major (i.e. we compute A @ B^T), ldb = N-row stride
// EPI: 0=bias, 1=bias+relu, 2=bias+residual, 3=attn-scores (scale+mask), 4=plain
// Batch index z decomposed as bb = z>>4, hh = z&15 (H=16); strides passed per
// operand. Non-batched GEMMs use gridDim.z==1 and zero strides.
// ---------------------------------------------------------------------------
template<int BM, int BN, int WM, int WN, int TRB, int EPI>
__global__ void mma_gemm(const float* __restrict__ Ag, const float* __restrict__ Bg,
                         const float* __restrict__ bias, const float* __restrict__ Res,
                         const int* __restrict__ mask, float* __restrict__ Cg,
                         int M, int N, int K, int lda, int ldb, int ldc,
                         long sAb, long sAh, long sBb, long sBh, long sCb, long sCh) {
    constexpr int BK = 16;
    constexpr int NWN = BN / WN;            // warps along N
    constexpr int NWARP = (BM / WM) * NWN;
    constexpr int T = NWARP * 32;
    constexpr int MA = WM / 16;             // m16 atoms per warp
    constexpr int NA = WN / 8;              // n8 atoms per warp

    __shared__ float As[BM][BK + 4];        // stride 20: conflict-free frag reads
    __shared__ float Bs[BK][BN + 8];        // stride%32==8: conflict-free frag reads

    int tid = threadIdx.x;
    int lane = tid & 31, wid = tid >> 5;
    int wm = wid / NWN, wn = wid % NWN;
    int gid = lane >> 2, tg = lane & 3;
    int bx = blockIdx.x, by = blockIdx.y, z = blockIdx.z;
    int bb = z >> 4, hh = z & 15;

    const float* A = Ag + (size_t)bb * sAb + (size_t)hh * sAh + (size_t)(by * BM) * lda;
    const float* Bp = Bg + (size_t)bb * sBb + (size_t)hh * sBh;
    float* C = Cg + (size_t)bb * sCb + (size_t)hh * sCh;

    float acc[MA][NA][4] = {};

    for (int k0 = 0; k0 < K; k0 += BK) {
        // ---- load A tile: BM x 16 (float4 per thread iter) ----
        for (int i = tid; i < BM * 4; i += T) {
            int r = i >> 2, q = (i & 3) << 2;
            float4 v = *(const float4*)(A + (size_t)r * lda + k0 + q);
            As[r][q + 0] = to_tf32(v.x);
            As[r][q + 1] = to_tf32(v.y);
            As[r][q + 2] = to_tf32(v.z);
            As[r][q + 3] = to_tf32(v.w);
        }
        // ---- load B tile: 16 x BN ----
        if (TRB == 0) {
            for (int i = tid; i < BN * 4; i += T) {
                int kr = i / (BN / 4), q = (i % (BN / 4)) * 4;
                float4 v = *(const float4*)(Bp + (size_t)(k0 + kr) * ldb + bx * BN + q);
                Bs[kr][q + 0] = to_tf32(v.x);
                Bs[kr][q + 1] = to_tf32(v.y);
                Bs[kr][q + 2] = to_tf32(v.z);
                Bs[kr][q + 3] = to_tf32(v.w);
            }
        } else {
            for (int i = tid; i < BN * 4; i += T) {
                int n = i >> 2, q = (i & 3) << 2;
                float4 v = *(const float4*)(Bp + (size_t)(bx * BN + n) * ldb + k0 + q);
                Bs[q + 0][n] = to_tf32(v.x);
                Bs[q + 1][n] = to_tf32(v.y);
                Bs[q + 2][n] = to_tf32(v.z);
                Bs[q + 3][n] = to_tf32(v.w);
            }
        }
        __syncthreads();

        #pragma unroll
        for (int ks = 0; ks < BK; ks += 8) {
            uint32_t af[MA][4], bf[NA][2];
            #pragma unroll
            for (int ma = 0; ma < MA; ma++) {
                int m = wm * WM + ma * 16 + gid;
                af[ma][0] = __float_as_uint(As[m][ks + tg]);
                af[ma][1] = __float_as_uint(As[m + 8][ks + tg]);
                af[ma][2] = __float_as_uint(As[m][ks + tg + 4]);
                af[ma][3] = __float_as_uint(As[m + 8][ks + tg + 4]);
            }
            #pragma unroll
            for (int na = 0; na < NA; na++) {
                int n = wn * WN + na * 8 + gid;
                bf[na][0] = __float_as_uint(Bs[ks + tg][n]);
                bf[na][1] = __float_as_uint(Bs[ks + tg + 4][n]);
            }
            #pragma unroll
            for (int ma = 0; ma < MA; ma++)
                #pragma unroll
                for (int na = 0; na < NA; na++)
                    mma_tf32(acc[ma][na], af[ma], bf[na]);
        }
        __syncthreads();
    }

    // ---- epilogue ----
    #pragma unroll
    for (int ma = 0; ma < MA; ma++) {
        #pragma unroll
        for (int na = 0; na < NA; na++) {
            int r = by * BM + wm * WM + ma * 16 + gid;
            int c = bx * BN + wn * WN + na * 8 + tg * 2;
            float o0 = acc[ma][na][0], o1 = acc[ma][na][1];
            float o2 = acc[ma][na][2], o3 = acc[ma][na][3];
            if (EPI == 0 || EPI == 1 || EPI == 2) {
                float b0 = bias[c], b1 = bias[c + 1];
                o0 += b0; o1 += b1; o2 += b0; o3 += b1;
            }
            if (EPI == 1) {
                o0 = fmaxf(o0, 0.f); o1 = fmaxf(o1, 0.f);
                o2 = fmaxf(o2, 0.f); o3 = fmaxf(o3, 0.f);
            }
            if (EPI == 2) {
                const float* rp0 = Res + (size_t)r * ldc + c;
                const float* rp1 = Res + (size_t)(r + 8) * ldc + c;
                o0 += rp0[0]; o1 += rp0[1];
                o2 += rp1[0]; o3 += rp1[1];
            }
            if (EPI == 3) {
                int m0 = mask[bb * S_ + c], m1 = mask[bb * S_ + c + 1];
                o0 = m0 ? o0 * 0.125f : -1e9f;
                o1 = m1 ? o1 * 0.125f : -1e9f;
                o2 = m0 ? o2 * 0.125f : -1e9f;
                o3 = m1 ? o3 * 0.125f : -1e9f;
            }
            float2 p0 = {o0, o1}, p1 = {o2, o3};
            *(float2*)(C + (size_t)r * ldc + c) = p0;
            *(float2*)(C + (size_t)(r + 8) * ldc + c) = p1;
        }
    }
}

// ---------------------------------------------------------------------------
// Block-wide allreduce helpers (256 threads = 8 warps)
// ---------------------------------------------------------------------------
__device__ __forceinline__ float allreduce_sum(float v, float* sh) {
    #pragma unroll
    for (int o = 16; o > 0; o >>= 1) v += __shfl_xor_sync(0xffffffffu, v, o);
    int lane = threadIdx.x & 31, wid = threadIdx.x >> 5;
    if (lane == 0) sh[wid] = v;
    __syncthreads();
    if (wid == 0) {
        float r = sh[lane & 7];
        #pragma unroll
        for (int o = 4; o > 0; o >>= 1) r += __shfl_xor_sync(0xffffffffu, r, o);
        if (lane == 0) sh[0] = r;
    }
    __syncthreads();
    float r = sh[0];
    __syncthreads();
    return r;
}

__device__ __forceinline__ float allreduce_max(float v, float* sh) {
    #pragma unroll
    for (int o = 16; o > 0; o >>= 1) v = fmaxf(v, __shfl_xor_sync(0xffffffffu, v, o));
    int lane = threadIdx.x & 31, wid = threadIdx.x >> 5;
    if (lane == 0) sh[wid] = v;
    __syncthreads();
    if (wid == 0) {
        float r = sh[lane & 7];
        #pragma unroll
        for (int o = 4; o > 0; o >>= 1) r = fmaxf(r, __shfl_xor_sync(0xffffffffu, r, o));
        if (lane == 0) sh[0] = r;
    }
    __syncthreads();
    float r = sh[0];
    __syncthreads();
    return r;
}

// ---------------------------------------------------------------------------
// LayerNorm: one block (256 thr) per row of D=1024. ddof=1, eps on std.
// ---------------------------------------------------------------------------
__global__ void layernorm_kernel(const float* __restrict__ x,
                                 const float* __restrict__ alpha,
                                 const float* __restrict__ beta,
                                 float* __restrict__ out) {
    __shared__ float sh[32];
    size_t row = blockIdx.x;
    const float* p = x + row * D_;
    float v[4];
    float s = 0.f;
    #pragma unroll
    for (int i = 0; i < 4; i++) { v[i] = p[threadIdx.x + i * 256]; s += v[i]; }
    s = allreduce_sum(s, sh);
    float mean = s * (1.0f / D_);
    float var = 0.f;
    #pragma unroll
    for (int i = 0; i < 4; i++) { float d = v[i] - mean; var += d * d; }
    var = allreduce_sum(var, sh) * (1.0f / (D_ - 1));   // Bessel correction
    float scale = alpha[0] / (sqrtf(var) + EPS_);       // eps added to std
    float bias = beta[0];
    float* o = out + row * D_;
    #pragma unroll
    for (int i = 0; i < 4; i++)
        o[threadIdx.x + i * 256] = (v[i] - mean) * scale + bias;
}

// ---------------------------------------------------------------------------
// Row softmax over S=2048, one block (256 thr) per row (B*H*S rows).
// ---------------------------------------------------------------------------
__global__ void softmax_kernel(float* __restrict__ scores) {
    __shared__ float sh[32];
    size_t row = blockIdx.x;
    float* p = scores + row * (size_t)S_;
    float v[8];
    float m = -INFINITY;
    #pragma unroll
    for (int i = 0; i < 8; i++) {
        v[i] = p[threadIdx.x + i * 256];
        m = fmaxf(m, v[i]);
    }
    m = allreduce_max(m, sh);
    float s = 0.f;
    #pragma unroll
    for (int i = 0; i < 8; i++) { v[i] = __expf(v[i] - m); s += v[i]; }
    s = allreduce_sum(s, sh);
    float inv = 1.0f / s;
    #pragma unroll
    for (int i = 0; i < 8; i++) p[threadIdx.x + i * 256] = v[i] * inv;
}

// ---------------------------------------------------------------------------
// Launch
// ---------------------------------------------------------------------------
extern "C" void kernel_launch(void* const* d_in, const int* in_sizes, int n_in,
                              void* d_out, int out_size) {
    const float* x    = (const float*)d_in[0];
    const int*   mask = (const int*)  d_in[1];
    const float* wq   = (const float*)d_in[2];
    const float* bq   = (const float*)d_in[3];
    const float* wk   = (const float*)d_in[4];
    const float* bk   = (const float*)d_in[5];
    const float* wv   = (const float*)d_in[6];
    const float* bv   = (const float*)d_in[7];
    const float* wo   = (const float*)d_in[8];
    const float* bo   = (const float*)d_in[9];
    const float* w1   = (const float*)d_in[10];
    const float* b1   = (const float*)d_in[11];
    const float* w2   = (const float*)d_in[12];
    const float* b2   = (const float*)d_in[13];
    const float* a1   = (const float*)d_in[14];
    const float* g1   = (const float*)d_in[15];
    const float* a2   = (const float*)d_in[16];
    const float* g2   = (const float*)d_in[17];
    float* out = (float*)d_out;

    float *n_, *q_, *k_, *v_, *ctx_, *x1_, *n2_, *ff1_, *sc_;
    cudaGetSymbolAddress((void**)&n_,   g_n);
    cudaGetSymbolAddress((void**)&q_,   g_q);
    cudaGetSymbolAddress((void**)&k_,   g_k);
    cudaGetSymbolAddress((void**)&v_,   g_v);
    cudaGetSymbolAddress((void**)&ctx_, g_ctx);
    cudaGetSymbolAddress((void**)&x1_,  g_x1);
    cudaGetSymbolAddress((void**)&n2_,  g_n2);
    cudaGetSymbolAddress((void**)&ff1_, g_ff1);
    cudaGetSymbolAddress((void**)&sc_,  g_scores);

    const long SD = (long)S_ * D_;       // per-batch stride of [b,s,h,dk] tensors
    const long SS = (long)S_ * S_;       // per-head score matrix size

    // ---- sublayer 1: pre-norm attention ----
    layernorm_kernel<<<M_, 256>>>(x, a1, g1, n_);

    dim3 gproj(D_ / 128, M_ / 128, 1);   // (8, 32)
    mma_gemm<128,128,64,32,0,0><<<gproj, 256>>>(n_, wq, bq, nullptr, nullptr, q_,
        M_, D_, D_, D_, D_, D_, 0,0,0,0,0,0);
    mma_gemm<128,128,64,32,0,0><<<gproj, 256>>>(n_, wk, bk, nullptr, nullptr, k_,
        M_, D_, D_, D_, D_, D_, 0,0,0,0,0,0);
    mma_gemm<128,128,64,32,0,0><<<gproj, 256>>>(n_, wv, bv, nullptr, nullptr, v_,
        M_, D_, D_, D_, D_, D_, 0,0,0,0,0,0);

    // scores[bh] = Q[bh] @ K[bh]^T * 0.125, masked  (TRB=1, EPI=3)
    mma_gemm<128,128,64,32,1,3><<<dim3(S_/128, S_/128, B_*H_), 256>>>(
        q_, k_, nullptr, nullptr, mask, sc_,
        S_, S_, DK_, D_, D_, S_,
        SD, DK_, SD, DK_, 16*SS, SS);

    softmax_kernel<<<B_ * H_ * S_, 256>>>(sc_);

    // ctx[bh] = attn[bh] @ V[bh]   (M=2048, N=64, K=2048)
    mma_gemm<128,64,64,32,0,4><<<dim3(1, S_/128, B_*H_), 128>>>(
        sc_, v_, nullptr, nullptr, nullptr, ctx_,
        S_, DK_, S_, S_, D_, D_,
        16*SS, SS, SD, DK_, SD, DK_);

    // O projection + residual
    mma_gemm<128,128,64,32,0,2><<<gproj, 256>>>(ctx_, wo, bo, x, nullptr, x1_,
        M_, D_, D_, D_, D_, D_, 0,0,0,0,0,0);

    // ---- sublayer 2: pre-norm FFN ----
    layernorm_kernel<<<M_, 256>>>(x1_, a2, g2, n2_);
    mma_gemm<128,128,64,32,0,1><<<dim3(DFF_/128, M_/128, 1), 256>>>(
        n2_, w1, b1, nullptr, nullptr, ff1_,
        M_, DFF_, D_, D_, DFF_, DFF_, 0,0,0,0,0,0);
    mma_gemm<128,128,64,32,0,2><<<dim3(D_/128, M_/128, 1), 256>>>(
        ff1_, w2, b2, x1_, nullptr, out,
        M_, D_, DFF_, DFF_, D_, D_, 0,0,0,0,0,0);
}

// round 6
// speedup vs baseline: 3.3928x; 1.8140x over previous
#include <cuda_runtime.h>
#include <math.h>
#include <stddef.h>
#include <stdint.h>

// Problem constants
#define B_    2
#define S_    2048
#define D_    1024
#define H_    16
#define DK_   64
#define DFF_  4096
#define M_    (B_ * S_)          // 4096 rows
#define EPS_  1e-6f

// ---------------------------------------------------------------------------
// Scratch (device globals: allocation-free workaround per harness rules)
// ---------------------------------------------------------------------------
__device__ float g_n  [(size_t)M_ * D_];
__device__ float g_q  [(size_t)M_ * D_];
__device__ float g_k  [(size_t)M_ * D_];
__device__ float g_v  [(size_t)M_ * D_];
__device__ float g_ctx[(size_t)M_ * D_];
__device__ float g_x1 [(size_t)M_ * D_];
__device__ float g_n2 [(size_t)M_ * D_];
__device__ float g_ff1[(size_t)M_ * DFF_];
__device__ float g_scores[(size_t)B_ * H_ * S_ * S_];   // 537 MB

// ---------------------------------------------------------------------------
// mma + cp.async helpers
// ---------------------------------------------------------------------------
__device__ __forceinline__ void mma_tf32(float* c, const uint32_t* a, const uint32_t* b) {
    asm volatile(
        "mma.sync.aligned.m16n8k8.row.col.f32.tf32.tf32.f32 "
        "{%0,%1,%2,%3}, {%4,%5,%6,%7}, {%8,%9}, {%0,%1,%2,%3};"
        : "+f"(c[0]), "+f"(c[1]), "+f"(c[2]), "+f"(c[3])
        : "r"(a[0]), "r"(a[1]), "r"(a[2]), "r"(a[3]), "r"(b[0]), "r"(b[1]));
}

__device__ __forceinline__ void cp16(float* s, const float* g) {
    uint32_t sa = (uint32_t)__cvta_generic_to_shared(s);
    asm volatile("cp.async.cg.shared.global [%0], [%1], 16;\n" :: "r"(sa), "l"(g));
}
__device__ __forceinline__ void cp_commit() {
    asm volatile("cp.async.commit_group;\n");
}
template<int N>
__device__ __forceinline__ void cp_wait() {
    asm volatile("cp.async.wait_group %0;\n" :: "n"(N));
}

// ---------------------------------------------------------------------------
// Batched tf32 tensor-core GEMM, cp.async double-buffered, BK=16,
// STATIC shared memory only (<=48KB: no attribute calls, capture-safe).
//   C[bh][M,N] = A[bh][M,K] @ B[bh][K,N] (+ epilogue)
// TRB=0: B row-major [K,N]; TRB=1: B is [N,K] row-major (compute A @ B^T)
// EPI: 0=bias, 1=bias+relu, 2=bias+residual, 3=attn-scores(scale+mask), 4=plain
// Raw fp32 bits feed the tf32 MMA (hardware truncates the mantissa).
// ---------------------------------------------------------------------------
template<int BM, int BN, int WM, int WN, int TRB, int EPI>
__global__ void __launch_bounds__(256, 2)
mma_gemm(const float* __restrict__ Ag, const float* __restrict__ Bg,
         const float* __restrict__ bias, const float* __restrict__ Res,
         const int* __restrict__ mask, float* __restrict__ Cg,
         int M, int N, int K, int lda, int ldb, int ldc,
         long sAb, long sAh, long sBb, long sBh, long sCb, long sCh) {
    constexpr int BK = 16;
    constexpr int NWN = BN / WN;            // warps along N
    constexpr int NWARP = (BM / WM) * NWN;
    constexpr int T = NWARP * 32;
    constexpr int MA = WM / 16;             // m16 atoms per warp
    constexpr int NA = WN / 8;              // n8 atoms per warp
    constexpr int ASTR = BK + 4;            // 20: conflict-free frag reads
    constexpr int BSTR = TRB ? (BK + 4) : (BN + 8);
    constexpr int ASZ = BM * ASTR;          // floats per A stage
    constexpr int BSZ = TRB ? (BN * BSTR) : (BK * BSTR);
    constexpr int ACH = BM * BK / 4;        // 16B chunks per A stage
    constexpr int BCH = (TRB ? BN * BK : BK * BN) / 4;

    __shared__ float As[2][ASZ];
    __shared__ float Bs[2][BSZ];

    int tid = threadIdx.x;
    int lane = tid & 31, wid = tid >> 5;
    int wm = wid / NWN, wn = wid % NWN;
    int gid = lane >> 2, tg = lane & 3;
    int bx = blockIdx.x, by = blockIdx.y, z = blockIdx.z;
    int bb = z >> 4;

    const float* A = Ag + (size_t)bb * sAb + (size_t)(z & 15) * sAh
                        + (size_t)(by * BM) * lda;
    const float* Bp = Bg + (size_t)bb * sBb + (size_t)(z & 15) * sBh;
    float* C = Cg + (size_t)bb * sCb + (size_t)(z & 15) * sCh;

    float acc[MA][NA][4] = {};

    // ---- stage loader: issue cp.async for k-tile kt into stage st ----
    auto load_stage = [&](int kt, int st) {
        float* as = As[st];
        float* bs = Bs[st];
        int k0 = kt * BK;
        #pragma unroll
        for (int i = tid; i < ACH; i += T) {
            int r = i >> 2, q = (i & 3) << 2;          // BK/4 = 4 chunks/row
            cp16(as + r * ASTR + q, A + (size_t)r * lda + k0 + q);
        }
        if (TRB == 0) {
            #pragma unroll
            for (int i = tid; i < BCH; i += T) {
                int kr = i / (BN / 4), q = (i % (BN / 4)) * 4;
                cp16(bs + kr * BSTR + q,
                     Bp + (size_t)(k0 + kr) * ldb + bx * BN + q);
            }
        } else {
            #pragma unroll
            for (int i = tid; i < BCH; i += T) {
                int n = i >> 2, q = (i & 3) << 2;
                cp16(bs + n * BSTR + q,
                     Bp + (size_t)(bx * BN + n) * ldb + k0 + q);
            }
        }
        cp_commit();
    };

    int tiles = K / BK;
    load_stage(0, 0);
    int cur = 0;

    for (int t = 0; t < tiles; t++) {
        if (t + 1 < tiles) {
            load_stage(t + 1, cur ^ 1);
            cp_wait<1>();
        } else {
            cp_wait<0>();
        }
        __syncthreads();

        const float* as = As[cur];
        const float* bs = Bs[cur];
        #pragma unroll
        for (int ks = 0; ks < BK; ks += 8) {
            uint32_t af[MA][4], bf[NA][2];
            #pragma unroll
            for (int ma = 0; ma < MA; ma++) {
                int m = wm * WM + ma * 16 + gid;
                af[ma][0] = __float_as_uint(as[m * ASTR + ks + tg]);
                af[ma][1] = __float_as_uint(as[(m + 8) * ASTR + ks + tg]);
                af[ma][2] = __float_as_uint(as[m * ASTR + ks + tg + 4]);
                af[ma][3] = __float_as_uint(as[(m + 8) * ASTR + ks + tg + 4]);
            }
            #pragma unroll
            for (int na = 0; na < NA; na++) {
                int n = wn * WN + na * 8 + gid;
                if (TRB == 0) {
                    bf[na][0] = __float_as_uint(bs[(ks + tg) * BSTR + n]);
                    bf[na][1] = __float_as_uint(bs[(ks + tg + 4) * BSTR + n]);
                } else {
                    bf[na][0] = __float_as_uint(bs[n * BSTR + ks + tg]);
                    bf[na][1] = __float_as_uint(bs[n * BSTR + ks + tg + 4]);
                }
            }
            #pragma unroll
            for (int ma = 0; ma < MA; ma++)
                #pragma unroll
                for (int na = 0; na < NA; na++)
                    mma_tf32(acc[ma][na], af[ma], bf[na]);
        }
        __syncthreads();
        cur ^= 1;
    }

    // ---- epilogue ----
    #pragma unroll
    for (int ma = 0; ma < MA; ma++) {
        #pragma unroll
        for (int na = 0; na < NA; na++) {
            int r = by * BM + wm * WM + ma * 16 + gid;
            int c = bx * BN + wn * WN + na * 8 + tg * 2;
            float o0 = acc[ma][na][0], o1 = acc[ma][na][1];
            float o2 = acc[ma][na][2], o3 = acc[ma][na][3];
            if (EPI == 0 || EPI == 1 || EPI == 2) {
                float b0 = bias[c], b1 = bias[c + 1];
                o0 += b0; o1 += b1; o2 += b0; o3 += b1;
            }
            if (EPI == 1) {
                o0 = fmaxf(o0, 0.f); o1 = fmaxf(o1, 0.f);
                o2 = fmaxf(o2, 0.f); o3 = fmaxf(o3, 0.f);
            }
            if (EPI == 2) {
                const float* rp0 = Res + (size_t)r * ldc + c;
                const float* rp1 = Res + (size_t)(r + 8) * ldc + c;
                o0 += rp0[0]; o1 += rp0[1];
                o2 += rp1[0]; o3 += rp1[1];
            }
            if (EPI == 3) {
                int m0 = mask[bb * S_ + c], m1 = mask[bb * S_ + c + 1];
                o0 = m0 ? o0 * 0.125f : -1e9f;
                o1 = m1 ? o1 * 0.125f : -1e9f;
                o2 = m0 ? o2 * 0.125f : -1e9f;
                o3 = m1 ? o3 * 0.125f : -1e9f;
            }
            float2 p0 = {o0, o1}, p1 = {o2, o3};
            *(float2*)(C + (size_t)r * ldc + c) = p0;
            *(float2*)(C + (size_t)(r + 8) * ldc + c) = p1;
        }
    }
}

// ---------------------------------------------------------------------------
// Block-wide allreduce helpers (256 threads = 8 warps)
// ---------------------------------------------------------------------------
__device__ __forceinline__ float allreduce_sum(float v, float* sh) {
    #pragma unroll
    for (int o = 16; o > 0; o >>= 1) v += __shfl_xor_sync(0xffffffffu, v, o);
    int lane = threadIdx.x & 31, wid = threadIdx.x >> 5;
    if (lane == 0) sh[wid] = v;
    __syncthreads();
    if (wid == 0) {
        float r = sh[lane & 7];
        #pragma unroll
        for (int o = 4; o > 0; o >>= 1) r += __shfl_xor_sync(0xffffffffu, r, o);
        if (lane == 0) sh[0] = r;
    }
    __syncthreads();
    float r = sh[0];
    __syncthreads();
    return r;
}

__device__ __forceinline__ float allreduce_max(float v, float* sh) {
    #pragma unroll
    for (int o = 16; o > 0; o >>= 1) v = fmaxf(v, __shfl_xor_sync(0xffffffffu, v, o));
    int lane = threadIdx.x & 31, wid = threadIdx.x >> 5;
    if (lane == 0) sh[wid] = v;
    __syncthreads();
    if (wid == 0) {
        float r = sh[lane & 7];
        #pragma unroll
        for (int o = 4; o > 0; o >>= 1) r = fmaxf(r, __shfl_xor_sync(0xffffffffu, r, o));
        if (lane == 0) sh[0] = r;
    }
    __syncthreads();
    float r = sh[0];
    __syncthreads();
    return r;
}

// ---------------------------------------------------------------------------
// LayerNorm: one block (256 thr) per row of D=1024. ddof=1, eps on std.
// ---------------------------------------------------------------------------
__global__ void layernorm_kernel(const float* __restrict__ x,
                                 const float* __restrict__ alpha,
                                 const float* __restrict__ beta,
                                 float* __restrict__ out) {
    __shared__ float sh[32];
    size_t row = blockIdx.x;
    const float* p = x + row * D_;
    float v[4];
    float s = 0.f;
    #pragma unroll
    for (int i = 0; i < 4; i++) { v[i] = p[threadIdx.x + i * 256]; s += v[i]; }
    s = allreduce_sum(s, sh);
    float mean = s * (1.0f / D_);
    float var = 0.f;
    #pragma unroll
    for (int i = 0; i < 4; i++) { float d = v[i] - mean; var += d * d; }
    var = allreduce_sum(var, sh) * (1.0f / (D_ - 1));   // Bessel correction
    float scale = alpha[0] / (sqrtf(var) + EPS_);       // eps added to std
    float bias = beta[0];
    float* o = out + row * D_;
    #pragma unroll
    for (int i = 0; i < 4; i++)
        o[threadIdx.x + i * 256] = (v[i] - mean) * scale + bias;
}

// ---------------------------------------------------------------------------
// Row softmax over S=2048, one block (256 thr) per row (B*H*S rows).
// ---------------------------------------------------------------------------
__global__ void softmax_kernel(float* __restrict__ scores) {
    __shared__ float sh[32];
    size_t row = blockIdx.x;
    float* p = scores + row * (size_t)S_;
    float v[8];
    float m = -INFINITY;
    #pragma unroll
    for (int i = 0; i < 8; i++) {
        v[i] = p[threadIdx.x + i * 256];
        m = fmaxf(m, v[i]);
    }
    m = allreduce_max(m, sh);
    float s = 0.f;
    #pragma unroll
    for (int i = 0; i < 8; i++) { v[i] = __expf(v[i] - m); s += v[i]; }
    s = allreduce_sum(s, sh);
    float inv = 1.0f / s;
    #pragma unroll
    for (int i = 0; i < 8; i++) p[threadIdx.x + i * 256] = v[i] * inv;
}

// ---------------------------------------------------------------------------
// Launch — no attribute calls, all static smem, capture-safe.
// ---------------------------------------------------------------------------
extern "C" void kernel_launch(void* const* d_in, const int* in_sizes, int n_in,
                              void* d_out, int out_size) {
    const float* x    = (const float*)d_in[0];
    const int*   mask = (const int*)  d_in[1];
    const float* wq   = (const float*)d_in[2];
    const float* bq   = (const float*)d_in[3];
    const float* wk   = (const float*)d_in[4];
    const float* bk   = (const float*)d_in[5];
    const float* wv   = (const float*)d_in[6];
    const float* bv   = (const float*)d_in[7];
    const float* wo   = (const float*)d_in[8];
    const float* bo   = (const float*)d_in[9];
    const float* w1   = (const float*)d_in[10];
    const float* b1   = (const float*)d_in[11];
    const float* w2   = (const float*)d_in[12];
    const float* b2   = (const float*)d_in[13];
    const float* a1   = (const float*)d_in[14];
    const float* g1   = (const float*)d_in[15];
    const float* a2   = (const float*)d_in[16];
    const float* g2   = (const float*)d_in[17];
    float* out = (float*)d_out;

    float *n_, *q_, *k_, *v_, *ctx_, *x1_, *n2_, *ff1_, *sc_;
    cudaGetSymbolAddress((void**)&n_,   g_n);
    cudaGetSymbolAddress((void**)&q_,   g_q);
    cudaGetSymbolAddress((void**)&k_,   g_k);
    cudaGetSymbolAddress((void**)&v_,   g_v);
    cudaGetSymbolAddress((void**)&ctx_, g_ctx);
    cudaGetSymbolAddress((void**)&x1_,  g_x1);
    cudaGetSymbolAddress((void**)&n2_,  g_n2);
    cudaGetSymbolAddress((void**)&ff1_, g_ff1);
    cudaGetSymbolAddress((void**)&sc_,  g_scores);

    const long SD = (long)S_ * D_;       // per-batch stride of [b,s,h,dk] tensors
    const long SS = (long)S_ * S_;       // per-head score matrix size

    // ---- sublayer 1: pre-norm attention ----
    layernorm_kernel<<<M_, 256>>>(x, a1, g1, n_);

    dim3 gproj(D_ / 128, M_ / 128, 1);   // (8, 32)
    mma_gemm<128,128,64,32,0,0><<<gproj, 256>>>(n_, wq, bq, nullptr, nullptr, q_,
        M_, D_, D_, D_, D_, D_, 0,0,0,0,0,0);
    mma_gemm<128,128,64,32,0,0><<<gproj, 256>>>(n_, wk, bk, nullptr, nullptr, k_,
        M_, D_, D_, D_, D_, D_, 0,0,0,0,0,0);
    mma_gemm<128,128,64,32,0,0><<<gproj, 256>>>(n_, wv, bv, nullptr, nullptr, v_,
        M_, D_, D_, D_, D_, D_, 0,0,0,0,0,0);

    // scores[bh] = Q[bh] @ K[bh]^T * 0.125, masked  (TRB=1, EPI=3)
    mma_gemm<128,128,64,32,1,3><<<dim3(S_/128, S_/128, B_*H_), 256>>>(
        q_, k_, nullptr, nullptr, mask, sc_,
        S_, S_, DK_, D_, D_, S_,
        SD, (long)DK_, SD, (long)DK_, 16*SS, SS);

    softmax_kernel<<<B_ * H_ * S_, 256>>>(sc_);

    // ctx[bh] = attn[bh] @ V[bh]   (M=2048, N=64, K=2048)
    mma_gemm<128,64,64,32,0,4><<<dim3(1, S_/128, B_*H_), 128>>>(
        sc_, v_, nullptr, nullptr, nullptr, ctx_,
        S_, DK_, S_, S_, D_, D_,
        16*SS, SS, SD, (long)DK_, SD, (long)DK_);

    // O projection + residual
    mma_gemm<128,128,64,32,0,2><<<gproj, 256>>>(ctx_, wo, bo, x, nullptr, x1_,
        M_, D_, D_, D_, D_, D_, 0,0,0,0,0,0);

    // ---- sublayer 2: pre-norm FFN ----
    layernorm_kernel<<<M_, 256>>>(x1_, a2, g2, n2_);
    mma_gemm<128,128,64,32,0,1><<<dim3(DFF_/128, M_/128, 1), 256>>>(
        n2_, w1, b1, nullptr, nullptr, ff1_,
        M_, DFF_, D_, D_, DFF_, DFF_, 0,0,0,0,0,0);
    mma_gemm<128,128,64,32,0,2><<<dim3(D_/128, M_/128, 1), 256>>>(
        ff1_, w2, b2, x1_, nullptr, out,
        M_, D_, DFF_, DFF_, D_, D_, 0,0,0,0,0,0);
}

// round 7
// speedup vs baseline: 3.6707x; 1.0819x over previous
#include <cuda_runtime.h>
#include <math.h>
#include <stddef.h>
#include <stdint.h>

// Problem constants
#define B_    2
#define S_    2048
#define D_    1024
#define H_    16
#define DK_   64
#define DFF_  4096
#define M_    (B_ * S_)          // 4096 rows
#define EPS_  1e-6f

// ---------------------------------------------------------------------------
// Scratch (device globals: allocation-free workaround per harness rules)
// ---------------------------------------------------------------------------
__device__ float g_n  [(size_t)M_ * D_];
__device__ float g_q  [(size_t)M_ * D_];
__device__ float g_k  [(size_t)M_ * D_];
__device__ float g_v  [(size_t)M_ * D_];
__device__ float g_ctx[(size_t)M_ * D_];
__device__ float g_x1 [(size_t)M_ * D_];
__device__ float g_n2 [(size_t)M_ * D_];
__device__ float g_ff1[(size_t)M_ * DFF_];
__device__ float g_scores[(size_t)B_ * H_ * S_ * S_];   // 537 MB
// rounded (tf32-exact) weights: wq|wk|wv|wo|w1|w2
__device__ float g_wr [(size_t)(4 * D_ * D_ + 2 * D_ * DFF_)];

// ---------------------------------------------------------------------------
// helpers
// ---------------------------------------------------------------------------
__device__ __forceinline__ float rnd_tf32(float x) {
    uint32_t u;
    asm("cvt.rna.tf32.f32 %0, %1;" : "=r"(u) : "f"(x));
    return __uint_as_float(u);
}

__device__ __forceinline__ void mma_tf32(float* c, const uint32_t* a, const uint32_t* b) {
    asm volatile(
        "mma.sync.aligned.m16n8k8.row.col.f32.tf32.tf32.f32 "
        "{%0,%1,%2,%3}, {%4,%5,%6,%7}, {%8,%9}, {%0,%1,%2,%3};"
        : "+f"(c[0]), "+f"(c[1]), "+f"(c[2]), "+f"(c[3])
        : "r"(a[0]), "r"(a[1]), "r"(a[2]), "r"(a[3]), "r"(b[0]), "r"(b[1]));
}

__device__ __forceinline__ void cp16(float* s, const float* g) {
    uint32_t sa = (uint32_t)__cvta_generic_to_shared(s);
    asm volatile("cp.async.cg.shared.global [%0], [%1], 16;\n" :: "r"(sa), "l"(g));
}
__device__ __forceinline__ void cp_commit() {
    asm volatile("cp.async.commit_group;\n");
}
template<int N>
__device__ __forceinline__ void cp_wait() {
    asm volatile("cp.async.wait_group %0;\n" :: "n"(N));
}

// ---------------------------------------------------------------------------
// Weight pre-round: out[i] = tf32_rna(in[i]); float4 grid-stride.
// ---------------------------------------------------------------------------
__global__ void roundw_kernel(const float* __restrict__ in, float* __restrict__ out,
                              int n4) {
    int i = blockIdx.x * blockDim.x + threadIdx.x;
    int stride = gridDim.x * blockDim.x;
    for (; i < n4; i += stride) {
        float4 v = ((const float4*)in)[i];
        v.x = rnd_tf32(v.x); v.y = rnd_tf32(v.y);
        v.z = rnd_tf32(v.z); v.w = rnd_tf32(v.w);
        ((float4*)out)[i] = v;
    }
}

// ---------------------------------------------------------------------------
// Batched tf32 tensor-core GEMM, cp.async double-buffered, BK=16,
// STATIC shared memory only (<=48KB, capture-safe).
//   C[bh][M,N] = A[bh][M,K] @ B[bh][K,N] (+ epilogue)
// TRB=0: B row-major [K,N]; TRB=1: B is [N,K] row-major (compute A @ B^T)
// EPI: 0=bias, 1=bias+relu, 2=bias+residual, 3=attn-scores(scale+mask), 4=plain
// RND: 1 = round output to tf32 (output feeds a later MMA), 0 = exact fp32.
// All MMA inputs are pre-rounded to tf32, so HW truncation is lossless.
// ---------------------------------------------------------------------------
template<int BM, int BN, int WM, int WN, int TRB, int EPI, int RND>
__global__ void
mma_gemm(const float* __restrict__ Ag, const float* __restrict__ Bg,
         const float* __restrict__ bias, const float* __restrict__ Res,
         const int* __restrict__ mask, float* __restrict__ Cg,
         int M, int N, int K, int lda, int ldb, int ldc,
         long sAb, long sAh, long sBb, long sBh, long sCb, long sCh) {
    constexpr int BK = 16;
    constexpr int NWN = BN / WN;            // warps along N
    constexpr int NWARP = (BM / WM) * NWN;
    constexpr int T = NWARP * 32;
    constexpr int MA = WM / 16;             // m16 atoms per warp
    constexpr int NA = WN / 8;              // n8 atoms per warp
    constexpr int ASTR = BK + 4;            // 20: conflict-free frag reads
    constexpr int BSTR = TRB ? (BK + 4) : (BN + 8);
    constexpr int ASZ = BM * ASTR;          // floats per A stage
    constexpr int BSZ = TRB ? (BN * BSTR) : (BK * BSTR);
    constexpr int ACH = BM * BK / 4;        // 16B chunks per A stage
    constexpr int BCH = (TRB ? BN * BK : BK * BN) / 4;

    __shared__ float As[2][ASZ];
    __shared__ float Bs[2][BSZ];

    int tid = threadIdx.x;
    int lane = tid & 31, wid = tid >> 5;
    int wm = wid / NWN, wn = wid % NWN;
    int gid = lane >> 2, tg = lane & 3;
    int bx = blockIdx.x, by = blockIdx.y, z = blockIdx.z;
    int bb = z >> 4;

    const float* A = Ag + (size_t)bb * sAb + (size_t)(z & 15) * sAh
                        + (size_t)(by * BM) * lda;
    const float* Bp = Bg + (size_t)bb * sBb + (size_t)(z & 15) * sBh;
    float* C = Cg + (size_t)bb * sCb + (size_t)(z & 15) * sCh;

    float acc[MA][NA][4] = {};

    // ---- stage loader: issue cp.async for k-tile kt into stage st ----
    auto load_stage = [&](int kt, int st) {
        float* as = As[st];
        float* bs = Bs[st];
        int k0 = kt * BK;
        #pragma unroll
        for (int i = tid; i < ACH; i += T) {
            int r = i >> 2, q = (i & 3) << 2;          // BK/4 = 4 chunks/row
            cp16(as + r * ASTR + q, A + (size_t)r * lda + k0 + q);
        }
        if (TRB == 0) {
            #pragma unroll
            for (int i = tid; i < BCH; i += T) {
                int kr = i / (BN / 4), q = (i % (BN / 4)) * 4;
                cp16(bs + kr * BSTR + q,
                     Bp + (size_t)(k0 + kr) * ldb + bx * BN + q);
            }
        } else {
            #pragma unroll
            for (int i = tid; i < BCH; i += T) {
                int n = i >> 2, q = (i & 3) << 2;
                cp16(bs + n * BSTR + q,
                     Bp + (size_t)(bx * BN + n) * ldb + k0 + q);
            }
        }
        cp_commit();
    };

    int tiles = K / BK;
    load_stage(0, 0);
    int cur = 0;

    for (int t = 0; t < tiles; t++) {
        if (t + 1 < tiles) {
            load_stage(t + 1, cur ^ 1);
            cp_wait<1>();
        } else {
            cp_wait<0>();
        }
        __syncthreads();

        const float* as = As[cur];
        const float* bs = Bs[cur];
        #pragma unroll
        for (int ks = 0; ks < BK; ks += 8) {
            uint32_t af[MA][4], bf[NA][2];
            #pragma unroll
            for (int ma = 0; ma < MA; ma++) {
                int m = wm * WM + ma * 16 + gid;
                af[ma][0] = __float_as_uint(as[m * ASTR + ks + tg]);
                af[ma][1] = __float_as_uint(as[(m + 8) * ASTR + ks + tg]);
                af[ma][2] = __float_as_uint(as[m * ASTR + ks + tg + 4]);
                af[ma][3] = __float_as_uint(as[(m + 8) * ASTR + ks + tg + 4]);
            }
            #pragma unroll
            for (int na = 0; na < NA; na++) {
                int n = wn * WN + na * 8 + gid;
                if (TRB == 0) {
                    bf[na][0] = __float_as_uint(bs[(ks + tg) * BSTR + n]);
                    bf[na][1] = __float_as_uint(bs[(ks + tg + 4) * BSTR + n]);
                } else {
                    bf[na][0] = __float_as_uint(bs[n * BSTR + ks + tg]);
                    bf[na][1] = __float_as_uint(bs[n * BSTR + ks + tg + 4]);
                }
            }
            #pragma unroll
            for (int ma = 0; ma < MA; ma++)
                #pragma unroll
                for (int na = 0; na < NA; na++)
                    mma_tf32(acc[ma][na], af[ma], bf[na]);
        }
        __syncthreads();
        cur ^= 1;
    }

    // ---- epilogue ----
    #pragma unroll
    for (int ma = 0; ma < MA; ma++) {
        #pragma unroll
        for (int na = 0; na < NA; na++) {
            int r = by * BM + wm * WM + ma * 16 + gid;
            int c = bx * BN + wn * WN + na * 8 + tg * 2;
            float o0 = acc[ma][na][0], o1 = acc[ma][na][1];
            float o2 = acc[ma][na][2], o3 = acc[ma][na][3];
            if (EPI == 0 || EPI == 1 || EPI == 2) {
                float b0 = bias[c], b1 = bias[c + 1];
                o0 += b0; o1 += b1; o2 += b0; o3 += b1;
            }
            if (EPI == 1) {
                o0 = fmaxf(o0, 0.f); o1 = fmaxf(o1, 0.f);
                o2 = fmaxf(o2, 0.f); o3 = fmaxf(o3, 0.f);
            }
            if (EPI == 2) {
                const float* rp0 = Res + (size_t)r * ldc + c;
                const float* rp1 = Res + (size_t)(r + 8) * ldc + c;
                o0 += rp0[0]; o1 += rp0[1];
                o2 += rp1[0]; o3 += rp1[1];
            }
            if (EPI == 3) {
                int m0 = mask[bb * S_ + c], m1 = mask[bb * S_ + c + 1];
                o0 = m0 ? o0 * 0.125f : -1e9f;
                o1 = m1 ? o1 * 0.125f : -1e9f;
                o2 = m0 ? o2 * 0.125f : -1e9f;
                o3 = m1 ? o3 * 0.125f : -1e9f;
            }
            if (RND) {
                o0 = rnd_tf32(o0); o1 = rnd_tf32(o1);
                o2 = rnd_tf32(o2); o3 = rnd_tf32(o3);
            }
            float2 p0 = {o0, o1}, p1 = {o2, o3};
            *(float2*)(C + (size_t)r * ldc + c) = p0;
            *(float2*)(C + (size_t)(r + 8) * ldc + c) = p1;
        }
    }
}

// ---------------------------------------------------------------------------
// Block-wide allreduce helpers (256 threads = 8 warps)
// ---------------------------------------------------------------------------
__device__ __forceinline__ float allreduce_sum(float v, float* sh) {
    #pragma unroll
    for (int o = 16; o > 0; o >>= 1) v += __shfl_xor_sync(0xffffffffu, v, o);
    int lane = threadIdx.x & 31, wid = threadIdx.x >> 5;
    if (lane == 0) sh[wid] = v;
    __syncthreads();
    if (wid == 0) {
        float r = sh[lane & 7];
        #pragma unroll
        for (int o = 4; o > 0; o >>= 1) r += __shfl_xor_sync(0xffffffffu, r, o);
        if (lane == 0) sh[0] = r;
    }
    __syncthreads();
    float r = sh[0];
    __syncthreads();
    return r;
}

__device__ __forceinline__ float allreduce_max(float v, float* sh) {
    #pragma unroll
    for (int o = 16; o > 0; o >>= 1) v = fmaxf(v, __shfl_xor_sync(0xffffffffu, v, o));
    int lane = threadIdx.x & 31, wid = threadIdx.x >> 5;
    if (lane == 0) sh[wid] = v;
    __syncthreads();
    if (wid == 0) {
        float r = sh[lane & 7];
        #pragma unroll
        for (int o = 4; o > 0; o >>= 1) r = fmaxf(r, __shfl_xor_sync(0xffffffffu, r, o));
        if (lane == 0) sh[0] = r;
    }
    __syncthreads();
    float r = sh[0];
    __syncthreads();
    return r;
}

// ---------------------------------------------------------------------------
// LayerNorm: one block (256 thr) per row of D=1024. ddof=1, eps on std.
// Output rounded to tf32 (it only feeds MMAs).
// ---------------------------------------------------------------------------
__global__ void layernorm_kernel(const float* __restrict__ x,
                                 const float* __restrict__ alpha,
                                 const float* __restrict__ beta,
                                 float* __restrict__ out) {
    __shared__ float sh[32];
    size_t row = blockIdx.x;
    const float* p = x + row * D_;
    float v[4];
    float s = 0.f;
    #pragma unroll
    for (int i = 0; i < 4; i++) { v[i] = p[threadIdx.x + i * 256]; s += v[i]; }
    s = allreduce_sum(s, sh);
    float mean = s * (1.0f / D_);
    float var = 0.f;
    #pragma unroll
    for (int i = 0; i < 4; i++) { float d = v[i] - mean; var += d * d; }
    var = allreduce_sum(var, sh) * (1.0f / (D_ - 1));   // Bessel correction
    float scale = alpha[0] / (sqrtf(var) + EPS_);       // eps added to std
    float bias = beta[0];
    float* o = out + row * D_;
    #pragma unroll
    for (int i = 0; i < 4; i++)
        o[threadIdx.x + i * 256] = rnd_tf32((v[i] - mean) * scale + bias);
}

// ---------------------------------------------------------------------------
// Row softmax over S=2048, one block (256 thr) per row (B*H*S rows).
// Output rounded to tf32 (feeds PV MMA).
// ---------------------------------------------------------------------------
__global__ void softmax_kernel(float* __restrict__ scores) {
    __shared__ float sh[32];
    size_t row = blockIdx.x;
    float* p = scores + row * (size_t)S_;
    float v[8];
    float m = -INFINITY;
    #pragma unroll
    for (int i = 0; i < 8; i++) {
        v[i] = p[threadIdx.x + i * 256];
        m = fmaxf(m, v[i]);
    }
    m = allreduce_max(m, sh);
    float s = 0.f;
    #pragma unroll
    for (int i = 0; i < 8; i++) { v[i] = __expf(v[i] - m); s += v[i]; }
    s = allreduce_sum(s, sh);
    float inv = 1.0f / s;
    #pragma unroll
    for (int i = 0; i < 8; i++) p[threadIdx.x + i * 256] = rnd_tf32(v[i] * inv);
}

// ---------------------------------------------------------------------------
// Launch — no attribute calls, all static smem, capture-safe.
// ---------------------------------------------------------------------------
extern "C" void kernel_launch(void* const* d_in, const int* in_sizes, int n_in,
                              void* d_out, int out_size) {
    const float* x    = (const float*)d_in[0];
    const int*   mask = (const int*)  d_in[1];
    const float* wq   = (const float*)d_in[2];
    const float* bq   = (const float*)d_in[3];
    const float* wk   = (const float*)d_in[4];
    const float* bk   = (const float*)d_in[5];
    const float* wv   = (const float*)d_in[6];
    const float* bv   = (const float*)d_in[7];
    const float* wo   = (const float*)d_in[8];
    const float* bo   = (const float*)d_in[9];
    const float* w1   = (const float*)d_in[10];
    const float* b1   = (const float*)d_in[11];
    const float* w2   = (const float*)d_in[12];
    const float* b2   = (const float*)d_in[13];
    const float* a1   = (const float*)d_in[14];
    const float* g1   = (const float*)d_in[15];
    const float* a2   = (const float*)d_in[16];
    const float* g2   = (const float*)d_in[17];
    float* out = (float*)d_out;

    float *n_, *q_, *k_, *v_, *ctx_, *x1_, *n2_, *ff1_, *sc_, *wr_;
    cudaGetSymbolAddress((void**)&n_,   g_n);
    cudaGetSymbolAddress((void**)&q_,   g_q);
    cudaGetSymbolAddress((void**)&k_,   g_k);
    cudaGetSymbolAddress((void**)&v_,   g_v);
    cudaGetSymbolAddress((void**)&ctx_, g_ctx);
    cudaGetSymbolAddress((void**)&x1_,  g_x1);
    cudaGetSymbolAddress((void**)&n2_,  g_n2);
    cudaGetSymbolAddress((void**)&ff1_, g_ff1);
    cudaGetSymbolAddress((void**)&sc_,  g_scores);
    cudaGetSymbolAddress((void**)&wr_,  g_wr);

    const long DD = (long)D_ * D_;
    float* wqr = wr_;            // [0, DD)
    float* wkr = wr_ + DD;       // [DD, 2DD)
    float* wvr = wr_ + 2 * DD;
    float* wor = wr_ + 3 * DD;
    float* w1r = wr_ + 4 * DD;            // D*DFF
    float* w2r = wr_ + 4 * DD + (long)D_ * DFF_;

    // ---- pre-round weights to tf32 (exact MMA inputs) ----
    roundw_kernel<<<512, 256>>>(wq, wqr, DD / 4);
    roundw_kernel<<<512, 256>>>(wk, wkr, DD / 4);
    roundw_kernel<<<512, 256>>>(wv, wvr, DD / 4);
    roundw_kernel<<<512, 256>>>(wo, wor, DD / 4);
    roundw_kernel<<<512, 256>>>(w1, w1r, (int)((long)D_ * DFF_ / 4));
    roundw_kernel<<<512, 256>>>(w2, w2r, (int)((long)D_ * DFF_ / 4));

    const long SD = (long)S_ * D_;       // per-batch stride of [b,s,h,dk] tensors
    const long SS = (long)S_ * S_;       // per-head score matrix size

    // ---- sublayer 1: pre-norm attention ----
    layernorm_kernel<<<M_, 256>>>(x, a1, g1, n_);

    // big GEMMs: WM=64, WN=64, 4 warps = 128 threads, LDS/mma = 1.0
    dim3 gproj(D_ / 128, M_ / 128, 1);   // (8, 32)
    mma_gemm<128,128,64,64,0,0,1><<<gproj, 128>>>(n_, wqr, bq, nullptr, nullptr, q_,
        M_, D_, D_, D_, D_, D_, 0,0,0,0,0,0);
    mma_gemm<128,128,64,64,0,0,1><<<gproj, 128>>>(n_, wkr, bk, nullptr, nullptr, k_,
        M_, D_, D_, D_, D_, D_, 0,0,0,0,0,0);
    mma_gemm<128,128,64,64,0,0,1><<<gproj, 128>>>(n_, wvr, bv, nullptr, nullptr, v_,
        M_, D_, D_, D_, D_, D_, 0,0,0,0,0,0);

    // scores[bh] = Q[bh] @ K[bh]^T * 0.125, masked  (TRB=1, EPI=3; fp32 out)
    mma_gemm<128,128,64,64,1,3,0><<<dim3(S_/128, S_/128, B_*H_), 128>>>(
        q_, k_, nullptr, nullptr, mask, sc_,
        S_, S_, DK_, D_, D_, S_,
        SD, (long)DK_, SD, (long)DK_, 16*SS, SS);

    softmax_kernel<<<B_ * H_ * S_, 256>>>(sc_);

    // ctx[bh] = attn[bh] @ V[bh]   (M=2048, N=64, K=2048); round for O-proj MMA
    mma_gemm<128,64,64,32,0,4,1><<<dim3(1, S_/128, B_*H_), 128>>>(
        sc_, v_, nullptr, nullptr, nullptr, ctx_,
        S_, DK_, S_, S_, D_, D_,
        16*SS, SS, SD, (long)DK_, SD, (long)DK_);

    // O projection + residual (exact fp32 out)
    mma_gemm<128,128,64,64,0,2,0><<<gproj, 128>>>(ctx_, wor, bo, x, nullptr, x1_,
        M_, D_, D_, D_, D_, D_, 0,0,0,0,0,0);

    // ---- sublayer 2: pre-norm FFN ----
    layernorm_kernel<<<M_, 256>>>(x1_, a2, g2, n2_);
    mma_gemm<128,128,64,64,0,1,1><<<dim3(DFF_/128, M_/128, 1), 128>>>(
        n2_, w1r, b1, nullptr, nullptr, ff1_,
        M_, DFF_, D_, D_, DFF_, DFF_, 0,0,0,0,0,0);
    mma_gemm<128,128,64,64,0,2,0><<<dim3(D_/128, M_/128, 1), 128>>>(
        ff1_, w2r, b2, x1_, nullptr, out,
        M_, D_, DFF_, DFF_, D_, D_, 0,0,0,0,0,0);
}

// round 8
// speedup vs baseline: 4.0497x; 1.1032x over previous
#include <cuda_runtime.h>
#include <math.h>
#include <stddef.h>
#include <stdint.h>

// Problem constants
#define B_    2
#define S_    2048
#define D_    1024
#define H_    16
#define DK_   64
#define DFF_  4096
#define M_    (B_ * S_)          // 4096 rows
#define EPS_  1e-6f

// ---------------------------------------------------------------------------
// Scratch (device globals: allocation-free workaround per harness rules)
// ---------------------------------------------------------------------------
__device__ float g_n  [(size_t)M_ * D_];
__device__ float g_q  [(size_t)M_ * D_];
__device__ float g_k  [(size_t)M_ * D_];
__device__ float g_v  [(size_t)M_ * D_];
__device__ float g_ctx[(size_t)M_ * D_];
__device__ float g_x1 [(size_t)M_ * D_];
__device__ float g_n2 [(size_t)M_ * D_];
__device__ float g_ff1[(size_t)M_ * DFF_];
// rounded (tf32-exact) weights: wq|wk|wv|wo|w1|w2
__device__ float g_wr [(size_t)(4 * D_ * D_ + 2 * D_ * DFF_)];

// ---------------------------------------------------------------------------
// helpers
// ---------------------------------------------------------------------------
__device__ __forceinline__ float rnd_tf32(float x) {
    uint32_t u;
    asm("cvt.rna.tf32.f32 %0, %1;" : "=r"(u) : "f"(x));
    return __uint_as_float(u);
}

__device__ __forceinline__ void mma_tf32(float* c, const uint32_t* a, const uint32_t* b) {
    asm volatile(
        "mma.sync.aligned.m16n8k8.row.col.f32.tf32.tf32.f32 "
        "{%0,%1,%2,%3}, {%4,%5,%6,%7}, {%8,%9}, {%0,%1,%2,%3};"
        : "+f"(c[0]), "+f"(c[1]), "+f"(c[2]), "+f"(c[3])
        : "r"(a[0]), "r"(a[1]), "r"(a[2]), "r"(a[3]), "r"(b[0]), "r"(b[1]));
}

__device__ __forceinline__ void cp16(float* s, const float* g) {
    uint32_t sa = (uint32_t)__cvta_generic_to_shared(s);
    asm volatile("cp.async.cg.shared.global [%0], [%1], 16;\n" :: "r"(sa), "l"(g));
}
__device__ __forceinline__ void cp_commit() {
    asm volatile("cp.async.commit_group;\n");
}
template<int N>
__device__ __forceinline__ void cp_wait() {
    asm volatile("cp.async.wait_group %0;\n" :: "n"(N));
}

// ---------------------------------------------------------------------------
// Weight pre-round: out[i] = tf32_rna(in[i]); float4 grid-stride.
// ---------------------------------------------------------------------------
__global__ void roundw_kernel(const float* __restrict__ in, float* __restrict__ out,
                              int n4) {
    int i = blockIdx.x * blockDim.x + threadIdx.x;
    int stride = gridDim.x * blockDim.x;
    for (; i < n4; i += stride) {
        float4 v = ((const float4*)in)[i];
        v.x = rnd_tf32(v.x); v.y = rnd_tf32(v.y);
        v.z = rnd_tf32(v.z); v.w = rnd_tf32(v.w);
        ((float4*)out)[i] = v;
    }
}

// ---------------------------------------------------------------------------
// Batched tf32 tensor-core GEMM, cp.async double-buffered, BK=16,
// STATIC shared memory only (<=48KB, capture-safe).
// TRB=0: B row-major [K,N]; TRB=1: B is [N,K] row-major (compute A @ B^T)
// EPI: 0=bias, 1=bias+relu, 2=bias+residual, 4=plain
// RND: 1 = round output to tf32 (feeds later MMA), 0 = exact fp32.
// ---------------------------------------------------------------------------
template<int BM, int BN, int WM, int WN, int TRB, int EPI, int RND>
__global__ void
mma_gemm(const float* __restrict__ Ag, const float* __restrict__ Bg,
         const float* __restrict__ bias, const float* __restrict__ Res,
         float* __restrict__ Cg,
         int M, int N, int K, int lda, int ldb, int ldc) {
    constexpr int BK = 16;
    constexpr int NWN = BN / WN;
    constexpr int NWARP = (BM / WM) * NWN;
    constexpr int T = NWARP * 32;
    constexpr int MA = WM / 16;
    constexpr int NA = WN / 8;
    constexpr int ASTR = BK + 4;
    constexpr int BSTR = TRB ? (BK + 4) : (BN + 8);
    constexpr int ASZ = BM * ASTR;
    constexpr int BSZ = TRB ? (BN * BSTR) : (BK * BSTR);
    constexpr int ACH = BM * BK / 4;
    constexpr int BCH = (TRB ? BN * BK : BK * BN) / 4;

    __shared__ float As[2][ASZ];
    __shared__ float Bs[2][BSZ];

    int tid = threadIdx.x;
    int lane = tid & 31, wid = tid >> 5;
    int wm = wid / NWN, wn = wid % NWN;
    int gid = lane >> 2, tg = lane & 3;
    int bx = blockIdx.x, by = blockIdx.y;

    const float* A = Ag + (size_t)(by * BM) * lda;
    const float* Bp = Bg;
    float* C = Cg;

    float acc[MA][NA][4] = {};

    auto load_stage = [&](int kt, int st) {
        float* as = As[st];
        float* bs = Bs[st];
        int k0 = kt * BK;
        #pragma unroll
        for (int i = tid; i < ACH; i += T) {
            int r = i >> 2, q = (i & 3) << 2;
            cp16(as + r * ASTR + q, A + (size_t)r * lda + k0 + q);
        }
        if (TRB == 0) {
            #pragma unroll
            for (int i = tid; i < BCH; i += T) {
                int kr = i / (BN / 4), q = (i % (BN / 4)) * 4;
                cp16(bs + kr * BSTR + q,
                     Bp + (size_t)(k0 + kr) * ldb + bx * BN + q);
            }
        } else {
            #pragma unroll
            for (int i = tid; i < BCH; i += T) {
                int n = i >> 2, q = (i & 3) << 2;
                cp16(bs + n * BSTR + q,
                     Bp + (size_t)(bx * BN + n) * ldb + k0 + q);
            }
        }
        cp_commit();
    };

    int tiles = K / BK;
    load_stage(0, 0);
    int cur = 0;

    for (int t = 0; t < tiles; t++) {
        if (t + 1 < tiles) {
            load_stage(t + 1, cur ^ 1);
            cp_wait<1>();
        } else {
            cp_wait<0>();
        }
        __syncthreads();

        const float* as = As[cur];
        const float* bs = Bs[cur];
        #pragma unroll
        for (int ks = 0; ks < BK; ks += 8) {
            uint32_t af[MA][4], bf[NA][2];
            #pragma unroll
            for (int ma = 0; ma < MA; ma++) {
                int m = wm * WM + ma * 16 + gid;
                af[ma][0] = __float_as_uint(as[m * ASTR + ks + tg]);
                af[ma][1] = __float_as_uint(as[(m + 8) * ASTR + ks + tg]);
                af[ma][2] = __float_as_uint(as[m * ASTR + ks + tg + 4]);
                af[ma][3] = __float_as_uint(as[(m + 8) * ASTR + ks + tg + 4]);
            }
            #pragma unroll
            for (int na = 0; na < NA; na++) {
                int n = wn * WN + na * 8 + gid;
                if (TRB == 0) {
                    bf[na][0] = __float_as_uint(bs[(ks + tg) * BSTR + n]);
                    bf[na][1] = __float_as_uint(bs[(ks + tg + 4) * BSTR + n]);
                } else {
                    bf[na][0] = __float_as_uint(bs[n * BSTR + ks + tg]);
                    bf[na][1] = __float_as_uint(bs[n * BSTR + ks + tg + 4]);
                }
            }
            #pragma unroll
            for (int ma = 0; ma < MA; ma++)
                #pragma unroll
                for (int na = 0; na < NA; na++)
                    mma_tf32(acc[ma][na], af[ma], bf[na]);
        }
        __syncthreads();
        cur ^= 1;
    }

    #pragma unroll
    for (int ma = 0; ma < MA; ma++) {
        #pragma unroll
        for (int na = 0; na < NA; na++) {
            int r = by * BM + wm * WM + ma * 16 + gid;
            int c = bx * BN + wn * WN + na * 8 + tg * 2;
            float o0 = acc[ma][na][0], o1 = acc[ma][na][1];
            float o2 = acc[ma][na][2], o3 = acc[ma][na][3];
            if (EPI == 0 || EPI == 1 || EPI == 2) {
                float b0 = bias[c], b1 = bias[c + 1];
                o0 += b0; o1 += b1; o2 += b0; o3 += b1;
            }
            if (EPI == 1) {
                o0 = fmaxf(o0, 0.f); o1 = fmaxf(o1, 0.f);
                o2 = fmaxf(o2, 0.f); o3 = fmaxf(o3, 0.f);
            }
            if (EPI == 2) {
                const float* rp0 = Res + (size_t)r * ldc + c;
                const float* rp1 = Res + (size_t)(r + 8) * ldc + c;
                o0 += rp0[0]; o1 += rp0[1];
                o2 += rp1[0]; o3 += rp1[1];
            }
            if (RND) {
                o0 = rnd_tf32(o0); o1 = rnd_tf32(o1);
                o2 = rnd_tf32(o2); o3 = rnd_tf32(o3);
            }
            float2 p0 = {o0, o1}, p1 = {o2, o3};
            *(float2*)(C + (size_t)r * ldc + c) = p0;
            *(float2*)(C + (size_t)(r + 8) * ldc + c) = p1;
        }
    }
}

// ---------------------------------------------------------------------------
// Flash attention: ctx = softmax(mask(QK^T/8)) @ V, fused, no score tensor.
// Grid: (S/64 q-tiles, B*H). 128 threads = 4 warps (2 along M, 2 along N).
// Q (64x64) in registers as A-frags; K tile in smem (overwritten by P);
// V tile in smem. Online softmax with reference semantics:
// s = mask ? s*0.125 : -1e9 BEFORE row max; exp in fp32; P rna-rounded.
// ---------------------------------------------------------------------------
__global__ void __launch_bounds__(128, 2)
flash_attn_kernel(const float* __restrict__ qg, const float* __restrict__ kg,
                  const float* __restrict__ vg, const int* __restrict__ maskg,
                  float* __restrict__ ctxg) {
    __shared__ float sKP[64 * 68];     // K tile, then P tile (17408 B)
    __shared__ float sV [64 * 72];     // V tile (18432 B)
    __shared__ int   sMask[64];
    __shared__ float sRedM[2][64];     // per-wn row max partials
    __shared__ float sRedS[2][64];     // per-wn row sum partials

    int tid = threadIdx.x;
    int lane = tid & 31, wid = tid >> 5;
    int wm = wid >> 1, wn = wid & 1;
    int gid = lane >> 2, tg = lane & 3;
    int qt = blockIdx.x, z = blockIdx.y;
    int bb = z >> 4, hh = z & 15;

    const size_t SD = (size_t)S_ * D_;
    const float* qp = qg + bb * SD + hh * DK_ + (size_t)(qt * 64) * D_;
    const float* kp = kg + bb * SD + hh * DK_;
    const float* vp = vg + bb * SD + hh * DK_;

    // ---- Q fragments (rows wm*32+ma*16+{gid,gid+8}, cols ks*8+{tg,tg+4}) ----
    uint32_t qf[2][8][4];
    #pragma unroll
    for (int ma = 0; ma < 2; ma++) {
        int r0 = wm * 32 + ma * 16 + gid;
        #pragma unroll
        for (int ks = 0; ks < 8; ks++) {
            int c0 = ks * 8 + tg;
            qf[ma][ks][0] = __float_as_uint(qp[(size_t)r0 * D_ + c0]);
            qf[ma][ks][1] = __float_as_uint(qp[(size_t)(r0 + 8) * D_ + c0]);
            qf[ma][ks][2] = __float_as_uint(qp[(size_t)r0 * D_ + c0 + 4]);
            qf[ma][ks][3] = __float_as_uint(qp[(size_t)(r0 + 8) * D_ + c0 + 4]);
        }
    }

    float oacc[2][4][4] = {};
    float m_run[2][2], l_run[2][2];
    #pragma unroll
    for (int ma = 0; ma < 2; ma++)
        #pragma unroll
        for (int h = 0; h < 2; h++) { m_run[ma][h] = -INFINITY; l_run[ma][h] = 0.f; }

    for (int kt = 0; kt < S_ / 64; kt++) {
        int k0 = kt * 64;
        // ---- load K, V tiles (cp.async), mask tile ----
        #pragma unroll
        for (int i = tid; i < 1024; i += 128) {
            int n = i >> 4, q4 = (i & 15) << 2;
            cp16(&sKP[n * 68 + q4], kp + (size_t)(k0 + n) * D_ + q4);
        }
        #pragma unroll
        for (int i = tid; i < 1024; i += 128) {
            int n = i >> 4, q4 = (i & 15) << 2;
            cp16(&sV[n * 72 + q4], vp + (size_t)(k0 + n) * D_ + q4);
        }
        if (tid < 64) sMask[tid] = maskg[bb * S_ + k0 + tid];
        cp_commit();
        cp_wait<0>();
        __syncthreads();

        // ---- S = Q @ K^T ----
        float sacc[2][4][4] = {};
        #pragma unroll
        for (int ks = 0; ks < 8; ks++) {
            uint32_t kf[4][2];
            #pragma unroll
            for (int na = 0; na < 4; na++) {
                int n = wn * 32 + na * 8 + gid;
                kf[na][0] = __float_as_uint(sKP[n * 68 + ks * 8 + tg]);
                kf[na][1] = __float_as_uint(sKP[n * 68 + ks * 8 + tg + 4]);
            }
            #pragma unroll
            for (int ma = 0; ma < 2; ma++)
                #pragma unroll
                for (int na = 0; na < 4; na++)
                    mma_tf32(sacc[ma][na], qf[ma][ks], kf[na]);
        }

        // ---- mask + scale + tile row-max (registers only) ----
        float tmax[2][2] = {{-INFINITY, -INFINITY}, {-INFINITY, -INFINITY}};
        #pragma unroll
        for (int ma = 0; ma < 2; ma++)
            #pragma unroll
            for (int na = 0; na < 4; na++) {
                int cb = wn * 32 + na * 8 + 2 * tg;
                int mk0 = sMask[cb], mk1 = sMask[cb + 1];
                float s0 = mk0 ? sacc[ma][na][0] * 0.125f : -1e9f;
                float s1 = mk1 ? sacc[ma][na][1] * 0.125f : -1e9f;
                float s2 = mk0 ? sacc[ma][na][2] * 0.125f : -1e9f;
                float s3 = mk1 ? sacc[ma][na][3] * 0.125f : -1e9f;
                sacc[ma][na][0] = s0; sacc[ma][na][1] = s1;
                sacc[ma][na][2] = s2; sacc[ma][na][3] = s3;
                tmax[ma][0] = fmaxf(tmax[ma][0], fmaxf(s0, s1));
                tmax[ma][1] = fmaxf(tmax[ma][1], fmaxf(s2, s3));
            }
        #pragma unroll
        for (int ma = 0; ma < 2; ma++)
            #pragma unroll
            for (int h = 0; h < 2; h++) {
                float v = tmax[ma][h];
                v = fmaxf(v, __shfl_xor_sync(0xffffffffu, v, 1));
                v = fmaxf(v, __shfl_xor_sync(0xffffffffu, v, 2));
                tmax[ma][h] = v;
            }
        if (tg == 0) {
            #pragma unroll
            for (int ma = 0; ma < 2; ma++) {
                sRedM[wn][wm * 32 + ma * 16 + gid]     = tmax[ma][0];
                sRedM[wn][wm * 32 + ma * 16 + gid + 8] = tmax[ma][1];
            }
        }
        __syncthreads();   // K fully consumed + maxes visible

        // ---- online stats, exp, write P (overwrites K buffer) ----
        float mnew[2][2], fsc[2][2], psum[2][2];
        #pragma unroll
        for (int ma = 0; ma < 2; ma++)
            #pragma unroll
            for (int h = 0; h < 2; h++) {
                int row = wm * 32 + ma * 16 + gid + h * 8;
                float mt = fmaxf(sRedM[0][row], sRedM[1][row]);
                float mn = fmaxf(m_run[ma][h], mt);
                mnew[ma][h] = mn;
                fsc[ma][h] = __expf(m_run[ma][h] - mn);
                psum[ma][h] = 0.f;
            }
        #pragma unroll
        for (int ma = 0; ma < 2; ma++) {
            int r0 = wm * 32 + ma * 16 + gid;
            #pragma unroll
            for (int na = 0; na < 4; na++) {
                int cb = wn * 32 + na * 8 + 2 * tg;
                float p0 = __expf(sacc[ma][na][0] - mnew[ma][0]);
                float p1 = __expf(sacc[ma][na][1] - mnew[ma][0]);
                float p2 = __expf(sacc[ma][na][2] - mnew[ma][1]);
                float p3 = __expf(sacc[ma][na][3] - mnew[ma][1]);
                psum[ma][0] += p0 + p1;
                psum[ma][1] += p2 + p3;
                sKP[r0 * 68 + cb]           = rnd_tf32(p0);
                sKP[r0 * 68 + cb + 1]       = rnd_tf32(p1);
                sKP[(r0 + 8) * 68 + cb]     = rnd_tf32(p2);
                sKP[(r0 + 8) * 68 + cb + 1] = rnd_tf32(p3);
            }
        }
        #pragma unroll
        for (int ma = 0; ma < 2; ma++)
            #pragma unroll
            for (int h = 0; h < 2; h++) {
                float v = psum[ma][h];
                v += __shfl_xor_sync(0xffffffffu, v, 1);
                v += __shfl_xor_sync(0xffffffffu, v, 2);
                psum[ma][h] = v;
            }
        if (tg == 0) {
            #pragma unroll
            for (int ma = 0; ma < 2; ma++) {
                sRedS[wn][wm * 32 + ma * 16 + gid]     = psum[ma][0];
                sRedS[wn][wm * 32 + ma * 16 + gid + 8] = psum[ma][1];
            }
        }
        __syncthreads();   // P + sums visible

        #pragma unroll
        for (int ma = 0; ma < 2; ma++)
            #pragma unroll
            for (int h = 0; h < 2; h++) {
                int row = wm * 32 + ma * 16 + gid + h * 8;
                l_run[ma][h] = l_run[ma][h] * fsc[ma][h]
                             + (sRedS[0][row] + sRedS[1][row]);
                m_run[ma][h] = mnew[ma][h];
            }
        // rescale O accumulators
        #pragma unroll
        for (int ma = 0; ma < 2; ma++)
            #pragma unroll
            for (int na = 0; na < 4; na++) {
                oacc[ma][na][0] *= fsc[ma][0];
                oacc[ma][na][1] *= fsc[ma][0];
                oacc[ma][na][2] *= fsc[ma][1];
                oacc[ma][na][3] *= fsc[ma][1];
            }

        // ---- O += P @ V ----
        #pragma unroll
        for (int ks = 0; ks < 8; ks++) {
            uint32_t af[2][4], vf[4][2];
            #pragma unroll
            for (int ma = 0; ma < 2; ma++) {
                int m0 = wm * 32 + ma * 16 + gid;
                af[ma][0] = __float_as_uint(sKP[m0 * 68 + ks * 8 + tg]);
                af[ma][1] = __float_as_uint(sKP[(m0 + 8) * 68 + ks * 8 + tg]);
                af[ma][2] = __float_as_uint(sKP[m0 * 68 + ks * 8 + tg + 4]);
                af[ma][3] = __float_as_uint(sKP[(m0 + 8) * 68 + ks * 8 + tg + 4]);
            }
            #pragma unroll
            for (int na = 0; na < 4; na++) {
                int n = wn * 32 + na * 8 + gid;
                vf[na][0] = __float_as_uint(sV[(ks * 8 + tg) * 72 + n]);
                vf[na][1] = __float_as_uint(sV[(ks * 8 + tg + 4) * 72 + n]);
            }
            #pragma unroll
            for (int ma = 0; ma < 2; ma++)
                #pragma unroll
                for (int na = 0; na < 4; na++)
                    mma_tf32(oacc[ma][na], af[ma], vf[na]);
        }
        __syncthreads();   // P, V consumed before next-iter overwrite
    }

    // ---- epilogue: ctx = O / l, rna-rounded (feeds O-proj MMA) ----
    float* cp_ = ctxg + bb * SD + hh * DK_;
    #pragma unroll
    for (int ma = 0; ma < 2; ma++) {
        int r0 = qt * 64 + wm * 32 + ma * 16 + gid;
        float inv0 = 1.0f / l_run[ma][0];
        float inv1 = 1.0f / l_run[ma][1];
        #pragma unroll
        for (int na = 0; na < 4; na++) {
            int c = wn * 32 + na * 8 + 2 * tg;
            float2 p0 = {rnd_tf32(oacc[ma][na][0] * inv0),
                         rnd_tf32(oacc[ma][na][1] * inv0)};
            float2 p1 = {rnd_tf32(oacc[ma][na][2] * inv1),
                         rnd_tf32(oacc[ma][na][3] * inv1)};
            *(float2*)(cp_ + (size_t)r0 * D_ + c) = p0;
            *(float2*)(cp_ + (size_t)(r0 + 8) * D_ + c) = p1;
        }
    }
}

// ---------------------------------------------------------------------------
// Block-wide allreduce helpers (256 threads = 8 warps)
// ---------------------------------------------------------------------------
__device__ __forceinline__ float allreduce_sum(float v, float* sh) {
    #pragma unroll
    for (int o = 16; o > 0; o >>= 1) v += __shfl_xor_sync(0xffffffffu, v, o);
    int lane = threadIdx.x & 31, wid = threadIdx.x >> 5;
    if (lane == 0) sh[wid] = v;
    __syncthreads();
    if (wid == 0) {
        float r = sh[lane & 7];
        #pragma unroll
        for (int o = 4; o > 0; o >>= 1) r += __shfl_xor_sync(0xffffffffu, r, o);
        if (lane == 0) sh[0] = r;
    }
    __syncthreads();
    float r = sh[0];
    __syncthreads();
    return r;
}

// ---------------------------------------------------------------------------
// LayerNorm: one block (256 thr) per row of D=1024. ddof=1, eps on std.
// Output rounded to tf32 (it only feeds MMAs).
// ---------------------------------------------------------------------------
__global__ void layernorm_kernel(const float* __restrict__ x,
                                 const float* __restrict__ alpha,
                                 const float* __restrict__ beta,
                                 float* __restrict__ out) {
    __shared__ float sh[32];
    size_t row = blockIdx.x;
    const float* p = x + row * D_;
    float v[4];
    float s = 0.f;
    #pragma unroll
    for (int i = 0; i < 4; i++) { v[i] = p[threadIdx.x + i * 256]; s += v[i]; }
    s = allreduce_sum(s, sh);
    float mean = s * (1.0f / D_);
    float var = 0.f;
    #pragma unroll
    for (int i = 0; i < 4; i++) { float d = v[i] - mean; var += d * d; }
    var = allreduce_sum(var, sh) * (1.0f / (D_ - 1));   // Bessel correction
    float scale = alpha[0] / (sqrtf(var) + EPS_);       // eps added to std
    float bias = beta[0];
    float* o = out + row * D_;
    #pragma unroll
    for (int i = 0; i < 4; i++)
        o[threadIdx.x + i * 256] = rnd_tf32((v[i] - mean) * scale + bias);
}

// ---------------------------------------------------------------------------
// Launch — no attribute calls, all static smem, capture-safe.
// ---------------------------------------------------------------------------
extern "C" void kernel_launch(void* const* d_in, const int* in_sizes, int n_in,
                              void* d_out, int out_size) {
    const float* x    = (const float*)d_in[0];
    const int*   mask = (const int*)  d_in[1];
    const float* wq   = (const float*)d_in[2];
    const float* bq   = (const float*)d_in[3];
    const float* wk   = (const float*)d_in[4];
    const float* bk   = (const float*)d_in[5];
    const float* wv   = (const float*)d_in[6];
    const float* bv   = (const float*)d_in[7];
    const float* wo   = (const float*)d_in[8];
    const float* bo   = (const float*)d_in[9];
    const float* w1   = (const float*)d_in[10];
    const float* b1   = (const float*)d_in[11];
    const float* w2   = (const float*)d_in[12];
    const float* b2   = (const float*)d_in[13];
    const float* a1   = (const float*)d_in[14];
    const float* g1   = (const float*)d_in[15];
    const float* a2   = (const float*)d_in[16];
    const float* g2   = (const float*)d_in[17];
    float* out = (float*)d_out;

    float *n_, *q_, *k_, *v_, *ctx_, *x1_, *n2_, *ff1_, *wr_;
    cudaGetSymbolAddress((void**)&n_,   g_n);
    cudaGetSymbolAddress((void**)&q_,   g_q);
    cudaGetSymbolAddress((void**)&k_,   g_k);
    cudaGetSymbolAddress((void**)&v_,   g_v);
    cudaGetSymbolAddress((void**)&ctx_, g_ctx);
    cudaGetSymbolAddress((void**)&x1_,  g_x1);
    cudaGetSymbolAddress((void**)&n2_,  g_n2);
    cudaGetSymbolAddress((void**)&ff1_, g_ff1);
    cudaGetSymbolAddress((void**)&wr_,  g_wr);

    const long DD = (long)D_ * D_;
    float* wqr = wr_;
    float* wkr = wr_ + DD;
    float* wvr = wr_ + 2 * DD;
    float* wor = wr_ + 3 * DD;
    float* w1r = wr_ + 4 * DD;
    float* w2r = wr_ + 4 * DD + (long)D_ * DFF_;

    // ---- pre-round weights to tf32 (exact MMA inputs) ----
    roundw_kernel<<<512, 256>>>(wq, wqr, DD / 4);
    roundw_kernel<<<512, 256>>>(wk, wkr, DD / 4);
    roundw_kernel<<<512, 256>>>(wv, wvr, DD / 4);
    roundw_kernel<<<512, 256>>>(wo, wor, DD / 4);
    roundw_kernel<<<512, 256>>>(w1, w1r, (int)((long)D_ * DFF_ / 4));
    roundw_kernel<<<512, 256>>>(w2, w2r, (int)((long)D_ * DFF_ / 4));

    // ---- sublayer 1: pre-norm attention ----
    layernorm_kernel<<<M_, 256>>>(x, a1, g1, n_);

    dim3 gproj(D_ / 128, M_ / 128, 1);   // (8, 32)
    mma_gemm<128,128,64,64,0,0,1><<<gproj, 128>>>(n_, wqr, bq, nullptr, q_,
        M_, D_, D_, D_, D_, D_);
    mma_gemm<128,128,64,64,0,0,1><<<gproj, 128>>>(n_, wkr, bk, nullptr, k_,
        M_, D_, D_, D_, D_, D_);
    mma_gemm<128,128,64,64,0,0,1><<<gproj, 128>>>(n_, wvr, bv, nullptr, v_,
        M_, D_, D_, D_, D_, D_);

    // fused attention: scores+softmax+PV in one kernel, no 537MB tensor
    flash_attn_kernel<<<dim3(S_ / 64, B_ * H_), 128>>>(q_, k_, v_, mask, ctx_);

    // O projection + residual (exact fp32 out)
    mma_gemm<128,128,64,64,0,2,0><<<gproj, 128>>>(ctx_, wor, bo, x, x1_,
        M_, D_, D_, D_, D_, D_);

    // ---- sublayer 2: pre-norm FFN ----
    layernorm_kernel<<<M_, 256>>>(x1_, a2, g2, n2_);
    mma_gemm<128,128,64,64,0,1,1><<<dim3(DFF_/128, M_/128, 1), 128>>>(
        n2_, w1r, b1, nullptr, ff1_,
        M_, DFF_, D_, D_, DFF_, DFF_);
    mma_gemm<128,128,64,64,0,2,0><<<dim3(D_/128, M_/128, 1), 128>>>(
        ff1_, w2r, b2, x1_, out,
        M_, D_, DFF_, DFF_, D_, D_);
}

// round 9
// speedup vs baseline: 4.3226x; 1.0674x over previous
#include <cuda_runtime.h>
#include <math.h>
#include <stddef.h>
#include <stdint.h>

// Problem constants
#define B_    2
#define S_    2048
#define D_    1024
#define H_    16
#define DK_   64
#define DFF_  4096
#define M_    (B_ * S_)          // 4096 rows
#define EPS_  1e-6f
#define D3_   (3 * D_)           // 3072

// ---------------------------------------------------------------------------
// Scratch (device globals: allocation-free workaround per harness rules)
// ---------------------------------------------------------------------------
__device__ float g_n   [(size_t)M_ * D_];
__device__ float g_qkv [(size_t)M_ * D3_];     // q|k|v interleaved per row
__device__ float g_ctx [(size_t)M_ * D_];
__device__ float g_x1  [(size_t)M_ * D_];
__device__ float g_n2  [(size_t)M_ * D_];
__device__ float g_ff1 [(size_t)M_ * DFF_];
// rounded (tf32-exact) weights: wqkv(concat [K,3D]) | wo | w1 | w2
__device__ float g_wr  [(size_t)(D_ * D3_ + D_ * D_ + 2 * D_ * DFF_)];
__device__ float g_bqkv[D3_];

// ---------------------------------------------------------------------------
// helpers
// ---------------------------------------------------------------------------
__device__ __forceinline__ float rnd_tf32(float x) {
    uint32_t u;
    asm("cvt.rna.tf32.f32 %0, %1;" : "=r"(u) : "f"(x));
    return __uint_as_float(u);
}

__device__ __forceinline__ void mma_tf32(float* c, const uint32_t* a, const uint32_t* b) {
    asm volatile(
        "mma.sync.aligned.m16n8k8.row.col.f32.tf32.tf32.f32 "
        "{%0,%1,%2,%3}, {%4,%5,%6,%7}, {%8,%9}, {%0,%1,%2,%3};"
        : "+f"(c[0]), "+f"(c[1]), "+f"(c[2]), "+f"(c[3])
        : "r"(a[0]), "r"(a[1]), "r"(a[2]), "r"(a[3]), "r"(b[0]), "r"(b[1]));
}

__device__ __forceinline__ void cp16(float* s, const float* g) {
    uint32_t sa = (uint32_t)__cvta_generic_to_shared(s);
    asm volatile("cp.async.cg.shared.global [%0], [%1], 16;\n" :: "r"(sa), "l"(g));
}
__device__ __forceinline__ void cp_commit() {
    asm volatile("cp.async.commit_group;\n");
}
template<int N>
__device__ __forceinline__ void cp_wait() {
    asm volatile("cp.async.wait_group %0;\n" :: "n"(N));
}

// ---------------------------------------------------------------------------
// Weight pre-round kernels
// ---------------------------------------------------------------------------
__global__ void roundw_kernel(const float* __restrict__ in, float* __restrict__ out,
                              int n4) {
    int i = blockIdx.x * blockDim.x + threadIdx.x;
    int stride = gridDim.x * blockDim.x;
    for (; i < n4; i += stride) {
        float4 v = ((const float4*)in)[i];
        v.x = rnd_tf32(v.x); v.y = rnd_tf32(v.y);
        v.z = rnd_tf32(v.z); v.w = rnd_tf32(v.w);
        ((float4*)out)[i] = v;
    }
}

// wqkv[k][n] (n<1024: wq, <2048: wk, else wv), rounded; also bias concat.
__global__ void round_qkv_kernel(const float* __restrict__ wq,
                                 const float* __restrict__ wk,
                                 const float* __restrict__ wv,
                                 const float* __restrict__ bq,
                                 const float* __restrict__ bk,
                                 const float* __restrict__ bv,
                                 float* __restrict__ wout,
                                 float* __restrict__ bout) {
    const int CH = D3_ / 4;                 // 768 float4 per row
    int i = blockIdx.x * blockDim.x + threadIdx.x;
    int stride = gridDim.x * blockDim.x;
    for (; i < D_ * CH; i += stride) {
        int k = i / CH, c4 = i % CH;
        int n = c4 * 4;
        const float* src = (n < D_)     ? (wq + (size_t)k * D_ + n)
                         : (n < 2 * D_) ? (wk + (size_t)k * D_ + n - D_)
                                        : (wv + (size_t)k * D_ + n - 2 * D_);
        float4 v = *(const float4*)src;
        v.x = rnd_tf32(v.x); v.y = rnd_tf32(v.y);
        v.z = rnd_tf32(v.z); v.w = rnd_tf32(v.w);
        ((float4*)wout)[i] = v;
    }
    int t = blockIdx.x * blockDim.x + threadIdx.x;
    if (t < D3_) {
        bout[t] = (t < D_) ? bq[t] : (t < 2 * D_) ? bk[t - D_] : bv[t - 2 * D_];
    }
}

// ---------------------------------------------------------------------------
// Batched tf32 tensor-core GEMM, cp.async double-buffered, BK=16,
// STATIC shared memory only (<=48KB, capture-safe).
// EPI: 0=bias, 1=bias+relu, 2=bias+residual
// RND: 1 = round output to tf32 (feeds later MMA), 0 = exact fp32.
// ---------------------------------------------------------------------------
template<int BM, int BN, int WM, int WN, int EPI, int RND>
__global__ void
mma_gemm(const float* __restrict__ Ag, const float* __restrict__ Bg,
         const float* __restrict__ bias, const float* __restrict__ Res,
         float* __restrict__ Cg,
         int M, int N, int K, int lda, int ldb, int ldc) {
    constexpr int BK = 16;
    constexpr int NWN = BN / WN;
    constexpr int NWARP = (BM / WM) * NWN;
    constexpr int T = NWARP * 32;
    constexpr int MA = WM / 16;
    constexpr int NA = WN / 8;
    constexpr int ASTR = BK + 4;
    constexpr int BSTR = BN + 8;
    constexpr int ASZ = BM * ASTR;
    constexpr int BSZ = BK * BSTR;
    constexpr int ACH = BM * BK / 4;
    constexpr int BCH = BK * BN / 4;

    __shared__ float As[2][ASZ];
    __shared__ float Bs[2][BSZ];

    int tid = threadIdx.x;
    int lane = tid & 31, wid = tid >> 5;
    int wm = wid / NWN, wn = wid % NWN;
    int gid = lane >> 2, tg = lane & 3;
    int bx = blockIdx.x, by = blockIdx.y;

    const float* A = Ag + (size_t)(by * BM) * lda;
    const float* Bp = Bg;
    float* C = Cg;

    float acc[MA][NA][4] = {};

    auto load_stage = [&](int kt, int st) {
        float* as = As[st];
        float* bs = Bs[st];
        int k0 = kt * BK;
        #pragma unroll
        for (int i = tid; i < ACH; i += T) {
            int r = i >> 2, q = (i & 3) << 2;
            cp16(as + r * ASTR + q, A + (size_t)r * lda + k0 + q);
        }
        #pragma unroll
        for (int i = tid; i < BCH; i += T) {
            int kr = i / (BN / 4), q = (i % (BN / 4)) * 4;
            cp16(bs + kr * BSTR + q,
                 Bp + (size_t)(k0 + kr) * ldb + bx * BN + q);
        }
        cp_commit();
    };

    int tiles = K / BK;
    load_stage(0, 0);
    int cur = 0;

    for (int t = 0; t < tiles; t++) {
        if (t + 1 < tiles) {
            load_stage(t + 1, cur ^ 1);
            cp_wait<1>();
        } else {
            cp_wait<0>();
        }
        __syncthreads();

        const float* as = As[cur];
        const float* bs = Bs[cur];
        #pragma unroll
        for (int ks = 0; ks < BK; ks += 8) {
            uint32_t af[MA][4], bf[NA][2];
            #pragma unroll
            for (int ma = 0; ma < MA; ma++) {
                int m = wm * WM + ma * 16 + gid;
                af[ma][0] = __float_as_uint(as[m * ASTR + ks + tg]);
                af[ma][1] = __float_as_uint(as[(m + 8) * ASTR + ks + tg]);
                af[ma][2] = __float_as_uint(as[m * ASTR + ks + tg + 4]);
                af[ma][3] = __float_as_uint(as[(m + 8) * ASTR + ks + tg + 4]);
            }
            #pragma unroll
            for (int na = 0; na < NA; na++) {
                int n = wn * WN + na * 8 + gid;
                bf[na][0] = __float_as_uint(bs[(ks + tg) * BSTR + n]);
                bf[na][1] = __float_as_uint(bs[(ks + tg + 4) * BSTR + n]);
            }
            #pragma unroll
            for (int ma = 0; ma < MA; ma++)
                #pragma unroll
                for (int na = 0; na < NA; na++)
                    mma_tf32(acc[ma][na], af[ma], bf[na]);
        }
        __syncthreads();
        cur ^= 1;
    }

    #pragma unroll
    for (int ma = 0; ma < MA; ma++) {
        #pragma unroll
        for (int na = 0; na < NA; na++) {
            int r = by * BM + wm * WM + ma * 16 + gid;
            int c = bx * BN + wn * WN + na * 8 + tg * 2;
            float o0 = acc[ma][na][0], o1 = acc[ma][na][1];
            float o2 = acc[ma][na][2], o3 = acc[ma][na][3];
            {
                float b0 = bias[c], b1 = bias[c + 1];
                o0 += b0; o1 += b1; o2 += b0; o3 += b1;
            }
            if (EPI == 1) {
                o0 = fmaxf(o0, 0.f); o1 = fmaxf(o1, 0.f);
                o2 = fmaxf(o2, 0.f); o3 = fmaxf(o3, 0.f);
            }
            if (EPI == 2) {
                const float* rp0 = Res + (size_t)r * ldc + c;
                const float* rp1 = Res + (size_t)(r + 8) * ldc + c;
                o0 += rp0[0]; o1 += rp0[1];
                o2 += rp1[0]; o3 += rp1[1];
            }
            if (RND) {
                o0 = rnd_tf32(o0); o1 = rnd_tf32(o1);
                o2 = rnd_tf32(o2); o3 = rnd_tf32(o3);
            }
            float2 p0 = {o0, o1}, p1 = {o2, o3};
            *(float2*)(C + (size_t)r * ldc + c) = p0;
            *(float2*)(C + (size_t)(r + 8) * ldc + c) = p1;
        }
    }
}

// ---------------------------------------------------------------------------
// Flash attention over interleaved qkv buffer (row stride 3D).
// Grid: (S/64 q-tiles, B*H). 128 threads = 4 warps (2 along M, 2 along N).
// K and V issued as separate cp.async groups: V load overlaps QK^T+softmax.
// Full mask row preloaded once. Online softmax, reference semantics.
// ---------------------------------------------------------------------------
__global__ void __launch_bounds__(128, 2)
flash_attn_kernel(const float* __restrict__ qkvg, const int* __restrict__ maskg,
                  float* __restrict__ ctxg) {
    __shared__ float sKP[64 * 68];     // K tile, then P tile
    __shared__ float sV [64 * 72];     // V tile
    __shared__ int   sMask[S_];        // full mask row (8KB)
    __shared__ float sRedM[2][64];
    __shared__ float sRedS[2][64];

    int tid = threadIdx.x;
    int lane = tid & 31, wid = tid >> 5;
    int wm = wid >> 1, wn = wid & 1;
    int gid = lane >> 2, tg = lane & 3;
    int qt = blockIdx.x, z = blockIdx.y;
    int bb = z >> 4, hh = z & 15;

    const size_t SD3 = (size_t)S_ * D3_;
    const float* qp = qkvg + bb * SD3 + hh * DK_ + (size_t)(qt * 64) * D3_;
    const float* kp = qkvg + bb * SD3 + D_ + hh * DK_;
    const float* vp = qkvg + bb * SD3 + 2 * D_ + hh * DK_;

    // ---- preload full mask row ----
    #pragma unroll
    for (int i = tid; i < S_ / 4; i += 128)
        ((int4*)sMask)[i] = ((const int4*)(maskg + bb * S_))[i];

    // ---- Q fragments ----
    uint32_t qf[2][8][4];
    #pragma unroll
    for (int ma = 0; ma < 2; ma++) {
        int r0 = wm * 32 + ma * 16 + gid;
        #pragma unroll
        for (int ks = 0; ks < 8; ks++) {
            int c0 = ks * 8 + tg;
            qf[ma][ks][0] = __float_as_uint(qp[(size_t)r0 * D3_ + c0]);
            qf[ma][ks][1] = __float_as_uint(qp[(size_t)(r0 + 8) * D3_ + c0]);
            qf[ma][ks][2] = __float_as_uint(qp[(size_t)r0 * D3_ + c0 + 4]);
            qf[ma][ks][3] = __float_as_uint(qp[(size_t)(r0 + 8) * D3_ + c0 + 4]);
        }
    }

    float oacc[2][4][4] = {};
    float m_run[2][2], l_run[2][2];
    #pragma unroll
    for (int ma = 0; ma < 2; ma++)
        #pragma unroll
        for (int h = 0; h < 2; h++) { m_run[ma][h] = -INFINITY; l_run[ma][h] = 0.f; }

    for (int kt = 0; kt < S_ / 64; kt++) {
        int k0 = kt * 64;
        // ---- K group, then V group (separate commits) ----
        #pragma unroll
        for (int i = tid; i < 1024; i += 128) {
            int n = i >> 4, q4 = (i & 15) << 2;
            cp16(&sKP[n * 68 + q4], kp + (size_t)(k0 + n) * D3_ + q4);
        }
        cp_commit();
        #pragma unroll
        for (int i = tid; i < 1024; i += 128) {
            int n = i >> 4, q4 = (i & 15) << 2;
            cp16(&sV[n * 72 + q4], vp + (size_t)(k0 + n) * D3_ + q4);
        }
        cp_commit();
        cp_wait<1>();          // K complete; V may still be in flight
        __syncthreads();

        // ---- S = Q @ K^T ----
        float sacc[2][4][4] = {};
        #pragma unroll
        for (int ks = 0; ks < 8; ks++) {
            uint32_t kf[4][2];
            #pragma unroll
            for (int na = 0; na < 4; na++) {
                int n = wn * 32 + na * 8 + gid;
                kf[na][0] = __float_as_uint(sKP[n * 68 + ks * 8 + tg]);
                kf[na][1] = __float_as_uint(sKP[n * 68 + ks * 8 + tg + 4]);
            }
            #pragma unroll
            for (int ma = 0; ma < 2; ma++)
                #pragma unroll
                for (int na = 0; na < 4; na++)
                    mma_tf32(sacc[ma][na], qf[ma][ks], kf[na]);
        }

        // ---- mask + scale + tile row-max ----
        float tmax[2][2] = {{-INFINITY, -INFINITY}, {-INFINITY, -INFINITY}};
        #pragma unroll
        for (int ma = 0; ma < 2; ma++)
            #pragma unroll
            for (int na = 0; na < 4; na++) {
                int cb = wn * 32 + na * 8 + 2 * tg;
                int mk0 = sMask[k0 + cb], mk1 = sMask[k0 + cb + 1];
                float s0 = mk0 ? sacc[ma][na][0] * 0.125f : -1e9f;
                float s1 = mk1 ? sacc[ma][na][1] * 0.125f : -1e9f;
                float s2 = mk0 ? sacc[ma][na][2] * 0.125f : -1e9f;
                float s3 = mk1 ? sacc[ma][na][3] * 0.125f : -1e9f;
                sacc[ma][na][0] = s0; sacc[ma][na][1] = s1;
                sacc[ma][na][2] = s2; sacc[ma][na][3] = s3;
                tmax[ma][0] = fmaxf(tmax[ma][0], fmaxf(s0, s1));
                tmax[ma][1] = fmaxf(tmax[ma][1], fmaxf(s2, s3));
            }
        #pragma unroll
        for (int ma = 0; ma < 2; ma++)
            #pragma unroll
            for (int h = 0; h < 2; h++) {
                float v = tmax[ma][h];
                v = fmaxf(v, __shfl_xor_sync(0xffffffffu, v, 1));
                v = fmaxf(v, __shfl_xor_sync(0xffffffffu, v, 2));
                tmax[ma][h] = v;
            }
        if (tg == 0) {
            #pragma unroll
            for (int ma = 0; ma < 2; ma++) {
                sRedM[wn][wm * 32 + ma * 16 + gid]     = tmax[ma][0];
                sRedM[wn][wm * 32 + ma * 16 + gid + 8] = tmax[ma][1];
            }
        }
        __syncthreads();   // K consumed + maxes visible

        // ---- online stats, exp, write P (overwrites K buffer) ----
        float mnew[2][2], fsc[2][2], psum[2][2];
        #pragma unroll
        for (int ma = 0; ma < 2; ma++)
            #pragma unroll
            for (int h = 0; h < 2; h++) {
                int row = wm * 32 + ma * 16 + gid + h * 8;
                float mt = fmaxf(sRedM[0][row], sRedM[1][row]);
                float mn = fmaxf(m_run[ma][h], mt);
                mnew[ma][h] = mn;
                fsc[ma][h] = __expf(m_run[ma][h] - mn);
                psum[ma][h] = 0.f;
            }
        #pragma unroll
        for (int ma = 0; ma < 2; ma++) {
            int r0 = wm * 32 + ma * 16 + gid;
            #pragma unroll
            for (int na = 0; na < 4; na++) {
                int cb = wn * 32 + na * 8 + 2 * tg;
                float p0 = __expf(sacc[ma][na][0] - mnew[ma][0]);
                float p1 = __expf(sacc[ma][na][1] - mnew[ma][0]);
                float p2 = __expf(sacc[ma][na][2] - mnew[ma][1]);
                float p3 = __expf(sacc[ma][na][3] - mnew[ma][1]);
                psum[ma][0] += p0 + p1;
                psum[ma][1] += p2 + p3;
                sKP[r0 * 68 + cb]           = rnd_tf32(p0);
                sKP[r0 * 68 + cb + 1]       = rnd_tf32(p1);
                sKP[(r0 + 8) * 68 + cb]     = rnd_tf32(p2);
                sKP[(r0 + 8) * 68 + cb + 1] = rnd_tf32(p3);
            }
        }
        #pragma unroll
        for (int ma = 0; ma < 2; ma++)
            #pragma unroll
            for (int h = 0; h < 2; h++) {
                float v = psum[ma][h];
                v += __shfl_xor_sync(0xffffffffu, v, 1);
                v += __shfl_xor_sync(0xffffffffu, v, 2);
                psum[ma][h] = v;
            }
        if (tg == 0) {
            #pragma unroll
            for (int ma = 0; ma < 2; ma++) {
                sRedS[wn][wm * 32 + ma * 16 + gid]     = psum[ma][0];
                sRedS[wn][wm * 32 + ma * 16 + gid + 8] = psum[ma][1];
            }
        }
        cp_wait<0>();      // V complete (per-thread) before barrier
        __syncthreads();   // P + sums + V visible

        #pragma unroll
        for (int ma = 0; ma < 2; ma++)
            #pragma unroll
            for (int h = 0; h < 2; h++) {
                int row = wm * 32 + ma * 16 + gid + h * 8;
                l_run[ma][h] = l_run[ma][h] * fsc[ma][h]
                             + (sRedS[0][row] + sRedS[1][row]);
                m_run[ma][h] = mnew[ma][h];
            }
        #pragma unroll
        for (int ma = 0; ma < 2; ma++)
            #pragma unroll
            for (int na = 0; na < 4; na++) {
                oacc[ma][na][0] *= fsc[ma][0];
                oacc[ma][na][1] *= fsc[ma][0];
                oacc[ma][na][2] *= fsc[ma][1];
                oacc[ma][na][3] *= fsc[ma][1];
            }

        // ---- O += P @ V ----
        #pragma unroll
        for (int ks = 0; ks < 8; ks++) {
            uint32_t af[2][4], vf[4][2];
            #pragma unroll
            for (int ma = 0; ma < 2; ma++) {
                int m0 = wm * 32 + ma * 16 + gid;
                af[ma][0] = __float_as_uint(sKP[m0 * 68 + ks * 8 + tg]);
                af[ma][1] = __float_as_uint(sKP[(m0 + 8) * 68 + ks * 8 + tg]);
                af[ma][2] = __float_as_uint(sKP[m0 * 68 + ks * 8 + tg + 4]);
                af[ma][3] = __float_as_uint(sKP[(m0 + 8) * 68 + ks * 8 + tg + 4]);
            }
            #pragma unroll
            for (int na = 0; na < 4; na++) {
                int n = wn * 32 + na * 8 + gid;
                vf[na][0] = __float_as_uint(sV[(ks * 8 + tg) * 72 + n]);
                vf[na][1] = __float_as_uint(sV[(ks * 8 + tg + 4) * 72 + n]);
            }
            #pragma unroll
            for (int ma = 0; ma < 2; ma++)
                #pragma unroll
                for (int na = 0; na < 4; na++)
                    mma_tf32(oacc[ma][na], af[ma], vf[na]);
        }
        __syncthreads();   // P, V consumed before next-iter overwrite
    }

    // ---- epilogue: ctx = O / l, rna-rounded (feeds O-proj MMA) ----
    float* cp_ = ctxg + bb * (size_t)S_ * D_ + hh * DK_;
    #pragma unroll
    for (int ma = 0; ma < 2; ma++) {
        int r0 = qt * 64 + wm * 32 + ma * 16 + gid;
        float inv0 = 1.0f / l_run[ma][0];
        float inv1 = 1.0f / l_run[ma][1];
        #pragma unroll
        for (int na = 0; na < 4; na++) {
            int c = wn * 32 + na * 8 + 2 * tg;
            float2 p0 = {rnd_tf32(oacc[ma][na][0] * inv0),
                         rnd_tf32(oacc[ma][na][1] * inv0)};
            float2 p1 = {rnd_tf32(oacc[ma][na][2] * inv1),
                         rnd_tf32(oacc[ma][na][3] * inv1)};
            *(float2*)(cp_ + (size_t)r0 * D_ + c) = p0;
            *(float2*)(cp_ + (size_t)(r0 + 8) * D_ + c) = p1;
        }
    }
}

// ---------------------------------------------------------------------------
// Block-wide allreduce (256 threads = 8 warps)
// ---------------------------------------------------------------------------
__device__ __forceinline__ float allreduce_sum(float v, float* sh) {
    #pragma unroll
    for (int o = 16; o > 0; o >>= 1) v += __shfl_xor_sync(0xffffffffu, v, o);
    int lane = threadIdx.x & 31, wid = threadIdx.x >> 5;
    if (lane == 0) sh[wid] = v;
    __syncthreads();
    if (wid == 0) {
        float r = sh[lane & 7];
        #pragma unroll
        for (int o = 4; o > 0; o >>= 1) r += __shfl_xor_sync(0xffffffffu, r, o);
        if (lane == 0) sh[0] = r;
    }
    __syncthreads();
    float r = sh[0];
    __syncthreads();
    return r;
}

// ---------------------------------------------------------------------------
// LayerNorm: one block (256 thr) per row of D=1024. ddof=1, eps on std.
// Output rounded to tf32 (it only feeds MMAs).
// ---------------------------------------------------------------------------
__global__ void layernorm_kernel(const float* __restrict__ x,
                                 const float* __restrict__ alpha,
                                 const float* __restrict__ beta,
                                 float* __restrict__ out) {
    __shared__ float sh[32];
    size_t row = blockIdx.x;
    const float* p = x + row * D_;
    float v[4];
    float s = 0.f;
    #pragma unroll
    for (int i = 0; i < 4; i++) { v[i] = p[threadIdx.x + i * 256]; s += v[i]; }
    s = allreduce_sum(s, sh);
    float mean = s * (1.0f / D_);
    float var = 0.f;
    #pragma unroll
    for (int i = 0; i < 4; i++) { float d = v[i] - mean; var += d * d; }
    var = allreduce_sum(var, sh) * (1.0f / (D_ - 1));   // Bessel correction
    float scale = alpha[0] / (sqrtf(var) + EPS_);       // eps added to std
    float bias = beta[0];
    float* o = out + row * D_;
    #pragma unroll
    for (int i = 0; i < 4; i++)
        o[threadIdx.x + i * 256] = rnd_tf32((v[i] - mean) * scale + bias);
}

// ---------------------------------------------------------------------------
// Launch — no attribute calls, all static smem, capture-safe.
// ---------------------------------------------------------------------------
extern "C" void kernel_launch(void* const* d_in, const int* in_sizes, int n_in,
                              void* d_out, int out_size) {
    const float* x    = (const float*)d_in[0];
    const int*   mask = (const int*)  d_in[1];
    const float* wq   = (const float*)d_in[2];
    const float* bq   = (const float*)d_in[3];
    const float* wk   = (const float*)d_in[4];
    const float* bk   = (const float*)d_in[5];
    const float* wv   = (const float*)d_in[6];
    const float* bv   = (const float*)d_in[7];
    const float* wo   = (const float*)d_in[8];
    const float* bo   = (const float*)d_in[9];
    const float* w1   = (const float*)d_in[10];
    const float* b1   = (const float*)d_in[11];
    const float* w2   = (const float*)d_in[12];
    const float* b2   = (const float*)d_in[13];
    const float* a1   = (const float*)d_in[14];
    const float* g1   = (const float*)d_in[15];
    const float* a2   = (const float*)d_in[16];
    const float* g2   = (const float*)d_in[17];
    float* out = (float*)d_out;

    float *n_, *qkv_, *ctx_, *x1_, *n2_, *ff1_, *wr_, *bqkv_;
    cudaGetSymbolAddress((void**)&n_,    g_n);
    cudaGetSymbolAddress((void**)&qkv_,  g_qkv);
    cudaGetSymbolAddress((void**)&ctx_,  g_ctx);
    cudaGetSymbolAddress((void**)&x1_,   g_x1);
    cudaGetSymbolAddress((void**)&n2_,   g_n2);
    cudaGetSymbolAddress((void**)&ff1_,  g_ff1);
    cudaGetSymbolAddress((void**)&wr_,   g_wr);
    cudaGetSymbolAddress((void**)&bqkv_, g_bqkv);

    const long DD = (long)D_ * D_;
    float* wqkvr = wr_;                              // [K=1024, 3072]
    float* wor   = wr_ + (long)D_ * D3_;
    float* w1r   = wor + DD;
    float* w2r   = w1r + (long)D_ * DFF_;

    // ---- pre-round weights to tf32 (exact MMA inputs) ----
    round_qkv_kernel<<<512, 256>>>(wq, wk, wv, bq, bk, bv, wqkvr, bqkv_);
    roundw_kernel<<<512, 256>>>(wo, wor, (int)(DD / 4));
    roundw_kernel<<<512, 256>>>(w1, w1r, (int)((long)D_ * DFF_ / 4));
    roundw_kernel<<<512, 256>>>(w2, w2r, (int)((long)D_ * DFF_ / 4));

    // ---- sublayer 1: pre-norm attention ----
    layernorm_kernel<<<M_, 256>>>(x, a1, g1, n_);

    // fused QKV projection: [4096,1024] @ [1024,3072]
    mma_gemm<128,128,64,64,0,1><<<dim3(D3_ / 128, M_ / 128), 128>>>(
        n_, wqkvr, bqkv_, nullptr, qkv_, M_, D3_, D_, D_, D3_, D3_);

    // fused attention
    flash_attn_kernel<<<dim3(S_ / 64, B_ * H_), 128>>>(qkv_, mask, ctx_);

    // O projection + residual (exact fp32 out)
    mma_gemm<128,128,64,64,2,0><<<dim3(D_ / 128, M_ / 128), 128>>>(
        ctx_, wor, bo, x, x1_, M_, D_, D_, D_, D_, D_);

    // ---- sublayer 2: pre-norm FFN ----
    layernorm_kernel<<<M_, 256>>>(x1_, a2, g2, n2_);
    mma_gemm<128,128,64,64,1,1><<<dim3(DFF_ / 128, M_ / 128), 128>>>(
        n2_, w1r, b1, nullptr, ff1_, M_, DFF_, D_, D_, DFF_, DFF_);
    mma_gemm<128,128,64,64,2,0><<<dim3(D_ / 128, M_ / 128), 128>>>(
        ff1_, w2r, b2, x1_, out, M_, D_, DFF_, DFF_, D_, D_);
}